// round 7
// baseline (speedup 1.0000x reference)
#include <cuda_runtime.h>
#include <cuda_fp16.h>
#include <cuda_bf16.h>

// ---------------- problem constants ----------------
#define B      512
#define C1     64
#define C2     128
#define FLAT   2048
#define F1     512
#define F2     10
#define BN_EPS 1e-5f

// ---------------- device scratch ----------------
__device__ unsigned g_maxabs[4];                  // zero-init; atomicMax idempotent across replays
__device__ unsigned g_ctr1, g_ctr2;               // tail-block tickets (reset by tail each call)
__device__ __half g_qw1h[C1 * 32];                // conv1 ternary [oc][k pad 32]
__device__ __half g_qw2h[25 * C2 * C1];           // conv2 ternary [khkw][oc][ci]
__device__ __half g_qf1h[F1 * FLAT];              // fc1 ternary [f][k]
__device__ float  g_qf2[F2 * F1];
__device__ float g_pool1[B * 144 * C1];           // RAW pooled conv1 (pre-BN), [b][pixel][ci]
__device__ float g_p1sum[C1 * B], g_p1sq[C1 * B];
__device__ float g_scale1[C1], g_shift1[C1];
__device__ float g_p2sum[C2 * B], g_p2sq[C2 * B];
__device__ float g_scale2[C2], g_shift2[C2];
__device__ float g_h1[B * FLAT];                  // RAW pooled conv2 (pre-BN)
__device__ float g_fc1[B * F1];                   // RAW fc1 (pre-BN)
__device__ float g_p3s[F1 * 8], g_p3q[F1 * 8];    // BN3 partials: [feature][b-tile]

// ---------------- asm helpers ----------------
__device__ __forceinline__ void cp16(__half* smem_dst, const __half* gsrc) {
    unsigned s = (unsigned)__cvta_generic_to_shared(smem_dst);
    asm volatile("cp.async.cg.shared.global [%0], [%1], 16;\n" :: "r"(s), "l"(gsrc));
}
#define CP_COMMIT() asm volatile("cp.async.commit_group;\n" ::: "memory")
#define CP_WAIT0()  asm volatile("cp.async.wait_group 0;\n" ::: "memory")

__device__ __forceinline__ void ldsm4(unsigned& r0, unsigned& r1, unsigned& r2, unsigned& r3,
                                      unsigned saddr) {
    asm volatile("ldmatrix.sync.aligned.m8n8.x4.shared.b16 {%0,%1,%2,%3}, [%4];"
                 : "=r"(r0), "=r"(r1), "=r"(r2), "=r"(r3) : "r"(saddr));
}
__device__ __forceinline__ void ldsm2(unsigned& r0, unsigned& r1, unsigned saddr) {
    asm volatile("ldmatrix.sync.aligned.m8n8.x2.shared.b16 {%0,%1}, [%2];"
                 : "=r"(r0), "=r"(r1) : "r"(saddr));
}

// ---------------- quantization ----------------
__global__ void k_absmax_all(const float* __restrict__ w0, const float* __restrict__ w1,
                             const float* __restrict__ w2, const float* __restrict__ w3) {
    const int slot = blockIdx.y;
    const float* w = (slot == 0) ? w0 : (slot == 1) ? w1 : (slot == 2) ? w2 : w3;
    const int n4 = ((slot == 0) ? 1600 : (slot == 1) ? 204800 : (slot == 2) ? 1048576 : 5120) >> 2;
    const float4* w4 = (const float4*)w;
    unsigned m = 0u;
    #pragma unroll 4
    for (int i = blockIdx.x * blockDim.x + threadIdx.x; i < n4; i += gridDim.x * blockDim.x) {
        float4 v = w4[i];
        m = max(m, __float_as_uint(fabsf(v.x)));
        m = max(m, __float_as_uint(fabsf(v.y)));
        m = max(m, __float_as_uint(fabsf(v.z)));
        m = max(m, __float_as_uint(fabsf(v.w)));
    }
    #pragma unroll
    for (int o = 16; o; o >>= 1)
        m = max(m, __shfl_xor_sync(0xffffffffu, m, o));
    if ((threadIdx.x & 31) == 0) atomicMax(&g_maxabs[slot], m);
}

__global__ void k_quant_all(const float* __restrict__ w0, const float* __restrict__ w1,
                            const float* __restrict__ w2, const float* __restrict__ w3) {
    const int slot = blockIdx.y;
    const float* w = (slot == 0) ? w0 : (slot == 1) ? w1 : (slot == 2) ? w2 : w3;
    const int n4 = ((slot == 0) ? 1600 : (slot == 1) ? 204800 : (slot == 2) ? 1048576 : 5120) >> 2;
    const float4* w4 = (const float4*)w;
    const float t = 0.05f * __uint_as_float(g_maxabs[slot]);
    #pragma unroll 2
    for (int i = blockIdx.x * blockDim.x + threadIdx.x; i < n4; i += gridDim.x * blockDim.x) {
        float4 v = w4[i];
        float q0 = (v.x > t) ? 1.0f : ((v.x < -t) ? -1.0f : 0.0f);
        float q1 = (v.y > t) ? 1.0f : ((v.y < -t) ? -1.0f : 0.0f);
        float q2 = (v.z > t) ? 1.0f : ((v.z < -t) ? -1.0f : 0.0f);
        float q3 = (v.w > t) ? 1.0f : ((v.w < -t) ? -1.0f : 0.0f);
        int base = 4 * i;
        if (slot == 0) {
            float qs[4] = {q0, q1, q2, q3};
            #pragma unroll
            for (int u = 0; u < 4; u++) {
                int idx = base + u, oc = idx / 25, k = idx - oc * 25;
                g_qw1h[oc * 32 + k] = __float2half(qs[u]);
            }
        } else if (slot == 1) {
            float qs[4] = {q0, q1, q2, q3};
            #pragma unroll
            for (int u = 0; u < 4; u++) {
                int idx = base + u;
                int oc = idx / 1600, rem = idx - oc * 1600, ci = rem / 25, kk = rem - ci * 25;
                g_qw2h[kk * (C2 * C1) + oc * C1 + ci] = __float2half(qs[u]);
            }
        } else if (slot == 2) {
            *(__half2*)&g_qf1h[base]     = __floats2half2_rn(q0, q1);
            *(__half2*)&g_qf1h[base + 2] = __floats2half2_rn(q2, q3);
        } else {
            *(float4*)&g_qf2[base] = make_float4(q0, q1, q2, q3);
        }
    }
}

// ---------------- conv1: fp16 mma + fused BN1 finalize in tail block ----------------
#define CV1_SMEM_BYTES (3136 + 5120 + 46080)
__global__ __launch_bounds__(256) void k_conv1(const float* __restrict__ x,
                                               const float* __restrict__ gamma,
                                               const float* __restrict__ beta) {
    extern __shared__ char c1sm[];
    float*  sxf = (float*)c1sm;
    __half* sA  = (__half*)(c1sm + 3136);
    __half* sB  = (__half*)(c1sm + 3136 + 5120);
    __shared__ float srs[64][9], srq[64][9];
    __shared__ bool slast;
    const int b = blockIdx.x, t = threadIdx.x;
    const int lane = t & 31, warp = t >> 5;
    const int l4 = lane >> 2, lm4 = lane & 3;

    for (int i = t; i < 784; i += 256) sxf[i] = x[b * 784 + i];
    #pragma unroll
    for (int j = 0; j < 2; j++) {
        int i = t + 256 * j;
        int oc = i >> 3, c4 = i & 7;
        *(uint2*)&sA[oc * 40 + c4 * 4] = *(const uint2*)&g_qw1h[oc * 32 + c4 * 4];
    }
    __syncthreads();

    {
        const int kp = t & 15, n0 = t >> 4;
        const int k0 = 2 * kp;
        const int kh0 = k0 / 5, kw0 = k0 - 5 * kh0;
        const int kh1 = (k0 + 1) / 5, kw1 = (k0 + 1) - 5 * kh1;
        const bool e0 = (k0 < 25), e1 = (k0 + 1 < 25);
        #pragma unroll 4
        for (int st = 0; st < 36; st++) {
            int n = n0 + 16 * st;
            int w = n >> 2, j = n & 3;
            int py = w / 12, px = w - 12 * py;
            int iy = 2 * py + (j >> 1), ix = 2 * px + (j & 1);
            float v0 = e0 ? sxf[(iy + kh0) * 28 + ix + kw0] : 0.f;
            float v1 = e1 ? sxf[(iy + kh1) * 28 + ix + kw1] : 0.f;
            *(__half2*)&sB[n * 40 + k0] = __floats2half2_rn(v0, v1);
        }
    }
    __syncthreads();

    unsigned a[4][2][4];
    #pragma unroll
    for (int mt = 0; mt < 4; mt++) {
        const __half* ap = sA + (mt * 16 + l4) * 40 + 2 * lm4;
        #pragma unroll
        for (int ks = 0; ks < 2; ks++) {
            a[mt][ks][0] = *(const unsigned*)(ap + 16 * ks);
            a[mt][ks][1] = *(const unsigned*)(ap + 16 * ks + 8 * 40);
            a[mt][ks][2] = *(const unsigned*)(ap + 16 * ks + 8);
            a[mt][ks][3] = *(const unsigned*)(ap + 16 * ks + 8 * 40 + 8);
        }
    }

    float s0a[4] = {0,0,0,0}, s1a[4] = {0,0,0,0};
    float q0a[4] = {0,0,0,0}, q1a[4] = {0,0,0,0};

    #pragma unroll
    for (int nt = 0; nt < 9; nt++) {
        const __half* bp = sB + (warp * 72 + nt * 8 + l4) * 40 + 2 * lm4;
        unsigned bf[2][2];
        #pragma unroll
        for (int ks = 0; ks < 2; ks++) {
            bf[ks][0] = *(const unsigned*)(bp + 16 * ks);
            bf[ks][1] = *(const unsigned*)(bp + 16 * ks + 8);
        }
        float c[4][4];
        #pragma unroll
        for (int mt = 0; mt < 4; mt++) {
            c[mt][0] = c[mt][1] = c[mt][2] = c[mt][3] = 0.f;
            #pragma unroll
            for (int ks = 0; ks < 2; ks++)
                asm volatile(
                    "mma.sync.aligned.m16n8k16.row.col.f32.f16.f16.f32 "
                    "{%0,%1,%2,%3},{%4,%5,%6,%7},{%8,%9},{%0,%1,%2,%3};"
                    : "+f"(c[mt][0]), "+f"(c[mt][1]), "+f"(c[mt][2]), "+f"(c[mt][3])
                    : "r"(a[mt][ks][0]), "r"(a[mt][ks][1]), "r"(a[mt][ks][2]), "r"(a[mt][ks][3]),
                      "r"(bf[ks][0]), "r"(bf[ks][1]));
        }
        const int wdw = warp * 18 + nt * 2 + (lm4 >> 1);
        #pragma unroll
        for (int mt = 0; mt < 4; mt++) {
            s0a[mt] += c[mt][0] + c[mt][1];
            q0a[mt] += c[mt][0]*c[mt][0] + c[mt][1]*c[mt][1];
            s1a[mt] += c[mt][2] + c[mt][3];
            q1a[mt] += c[mt][2]*c[mt][2] + c[mt][3]*c[mt][3];
            float m0 = fmaxf(c[mt][0], c[mt][1]);
            float m1 = fmaxf(c[mt][2], c[mt][3]);
            m0 = fmaxf(m0, __shfl_xor_sync(0xffffffffu, m0, 1));
            m1 = fmaxf(m1, __shfl_xor_sync(0xffffffffu, m1, 1));
            if ((lm4 & 1) == 0) {
                int oc = mt * 16 + l4;
                g_pool1[b * 9216 + wdw * 64 + oc]     = m0;
                g_pool1[b * 9216 + wdw * 64 + oc + 8] = m1;
            }
        }
    }

    #pragma unroll
    for (int mt = 0; mt < 4; mt++) {
        float s0 = s0a[mt], q0 = q0a[mt], s1 = s1a[mt], q1 = q1a[mt];
        s0 += __shfl_xor_sync(0xffffffffu, s0, 1); s0 += __shfl_xor_sync(0xffffffffu, s0, 2);
        q0 += __shfl_xor_sync(0xffffffffu, q0, 1); q0 += __shfl_xor_sync(0xffffffffu, q0, 2);
        s1 += __shfl_xor_sync(0xffffffffu, s1, 1); s1 += __shfl_xor_sync(0xffffffffu, s1, 2);
        q1 += __shfl_xor_sync(0xffffffffu, q1, 1); q1 += __shfl_xor_sync(0xffffffffu, q1, 2);
        if (lm4 == 0) {
            srs[mt * 16 + l4][warp] = s0;     srq[mt * 16 + l4][warp] = q0;
            srs[mt * 16 + l4 + 8][warp] = s1; srq[mt * 16 + l4 + 8][warp] = q1;
        }
    }
    __syncthreads();
    if (t < 64) {
        float S = 0.f, Q = 0.f;
        #pragma unroll
        for (int w = 0; w < 8; w++) { S += srs[t][w]; Q += srq[t][w]; }
        g_p1sum[t * B + b] = S;
        g_p1sq [t * B + b] = Q;
    }

    // ---- tail block: BN1 finalize (same reduction order as old k_bnfin1) ----
    __syncthreads();
    __threadfence();
    if (t == 0) slast = (atomicAdd(&g_ctr1, 1u) == (unsigned)(gridDim.x - 1));
    __syncthreads();
    if (!slast) return;
    if (t == 0) g_ctr1 = 0u;
    for (int c = warp; c < C1; c += 8) {
        const float4* ps = (const float4*)&g_p1sum[c * B];
        const float4* pq = (const float4*)&g_p1sq [c * B];
        float s = 0.f, q = 0.f;
        #pragma unroll
        for (int i = 0; i < 4; i++) {
            float4 v = ps[lane * 4 + i]; s += v.x + v.y + v.z + v.w;
            float4 u = pq[lane * 4 + i]; q += u.x + u.y + u.z + u.w;
        }
        #pragma unroll
        for (int o = 16; o; o >>= 1) {
            s += __shfl_xor_sync(0xffffffffu, s, o);
            q += __shfl_xor_sync(0xffffffffu, q, o);
        }
        if (lane == 0) {
            const float invN = 1.0f / (float)(B * 576);
            float mean = s * invN;
            float var  = q * invN - mean * mean;
            float sc = gamma[c] * rsqrtf(var + BN_EPS);
            g_scale1[c] = sc;
            g_shift1[c] = beta[c] - mean * sc;
        }
    }
}

// ---------------- conv2: fp16 mma implicit GEMM + fused BN2 finalize tail ---------------
#define CV2_CSTR 72
#define CV2_IMGH (144 * CV2_CSTR)
#define CV2_SA_H (4 * CV2_IMGH)
#define CV2_WBUF (C2 * CV2_CSTR)
#define CV2_SMEM_BYTES ((CV2_SA_H + 2 * CV2_WBUF) * 2)

__global__ __launch_bounds__(256, 1) void k_conv2(const float* __restrict__ gamma,
                                                  const float* __restrict__ beta) {
    extern __shared__ __half smh[];
    __half* sxh = smh;
    __half* sA0 = smh + CV2_SA_H;
    __half* sA1 = sA0 + CV2_WBUF;
    __shared__ bool slast;
    const int b4 = blockIdx.x * 4;
    const int t = threadIdx.x;
    const int lane = t & 31, warp = t >> 5;
    const int l4 = lane >> 2, lm4 = lane & 3;
    const int wm = warp >> 2, wn = warp & 3;
    const int m0w = wm * 64;

    {
        const __half* wsrc = g_qw2h;
        #pragma unroll
        for (int j = 0; j < 4; j++) {
            int idx = t + 256 * j;
            int oc = idx >> 3, c8 = idx & 7;
            cp16(sA0 + oc * CV2_CSTR + c8 * 8, wsrc + idx * 8);
        }
        CP_COMMIT();
    }

    for (int idx = t; idx < 4 * 144 * 32; idx += 256) {
        int img = idx / 4608, r = idx - img * 4608;
        int p = r >> 5, cp = r & 31;
        int ci0 = 2 * cp;
        float2 v = *(const float2*)&g_pool1[(b4 + img) * 9216 + p * 64 + ci0];
        float v0 = fmaxf(fmaf(g_scale1[ci0],     v.x, g_shift1[ci0]),     0.0f);
        float v1 = fmaxf(fmaf(g_scale1[ci0 + 1], v.y, g_shift1[ci0 + 1]), 0.0f);
        *(__half2*)&sxh[img * CV2_IMGH + p * CV2_CSTR + ci0] = __floats2half2_rn(v0, v1);
    }

    float c[4][8][4];
    #pragma unroll
    for (int i = 0; i < 4; i++)
        #pragma unroll
        for (int j = 0; j < 8; j++)
            #pragma unroll
            for (int r = 0; r < 4; r++) c[i][j][r] = 0.f;

    // ldmatrix byte addresses (shared space)
    const unsigned sxa  = (unsigned)__cvta_generic_to_shared(sxh);
    const unsigned sA0a = (unsigned)__cvta_generic_to_shared(sA0);
    const unsigned sA1a = (unsigned)__cvta_generic_to_shared(sA1);
    const unsigned aoff = ((m0w + (lane & 15)) * CV2_CSTR) * 2 + ((lane >> 4) << 4);
    const unsigned bln  = ((lane & 7) * CV2_CSTR) * 2 + (((lane >> 3) & 1) << 4);

    for (int khkw = 0; khkw < 25; khkw++) {
        const unsigned sAa = (khkw & 1) ? sA1a : sA0a;
        CP_WAIT0();
        __syncthreads();
        if (khkw < 24) {
            __half* dst = (khkw & 1) ? sA0 : sA1;
            const __half* wsrc = g_qw2h + (khkw + 1) * (C2 * C1);
            #pragma unroll
            for (int j = 0; j < 4; j++) {
                int idx = t + 256 * j;
                int oc = idx >> 3, c8 = idx & 7;
                cp16(dst + oc * CV2_CSTR + c8 * 8, wsrc + idx * 8);
            }
            CP_COMMIT();
        }
        const int kh = khkw / 5, kw = khkw - 5 * kh;
        const unsigned bbase = sxa + (wn * CV2_IMGH + (kh * 12 + kw) * CV2_CSTR) * 2 + bln;
        #pragma unroll
        for (int ks = 0; ks < 4; ks++) {
            const unsigned k0b = ks * 32;
            unsigned a[4][4], bf[8][2];
            #pragma unroll
            for (int mt = 0; mt < 4; mt++)
                ldsm4(a[mt][0], a[mt][1], a[mt][2], a[mt][3],
                      sAa + aoff + (unsigned)(mt * 16 * CV2_CSTR * 2) + k0b);
            #pragma unroll
            for (int nt = 0; nt < 8; nt++)
                ldsm2(bf[nt][0], bf[nt][1],
                      bbase + (unsigned)(nt * 12 * CV2_CSTR * 2) + k0b);
            #pragma unroll
            for (int mt = 0; mt < 4; mt++)
                #pragma unroll
                for (int nt = 0; nt < 8; nt++)
                    asm volatile(
                        "mma.sync.aligned.m16n8k16.row.col.f32.f16.f16.f32 "
                        "{%0,%1,%2,%3},{%4,%5,%6,%7},{%8,%9},{%0,%1,%2,%3};"
                        : "+f"(c[mt][nt][0]), "+f"(c[mt][nt][1]),
                          "+f"(c[mt][nt][2]), "+f"(c[mt][nt][3])
                        : "r"(a[mt][0]), "r"(a[mt][1]), "r"(a[mt][2]), "r"(a[mt][3]),
                          "r"(bf[nt][0]), "r"(bf[nt][1]));
        }
    }

    const int bimg = b4 + wn;
    #pragma unroll
    for (int mt = 0; mt < 4; mt++) {
        int r0 = m0w + mt * 16 + l4;
        #pragma unroll
        for (int tp = 0; tp < 4; tp++) {
            float pA = fmaxf(fmaxf(c[mt][2*tp][0], c[mt][2*tp][1]),
                             fmaxf(c[mt][2*tp+1][0], c[mt][2*tp+1][1]));
            float pB = fmaxf(fmaxf(c[mt][2*tp][2], c[mt][2*tp][3]),
                             fmaxf(c[mt][2*tp+1][2], c[mt][2*tp+1][3]));
            g_h1[bimg * FLAT + r0 * 16 + tp * 4 + lm4] = pA;
            g_h1[bimg * FLAT + (r0 + 8) * 16 + tp * 4 + lm4] = pB;
        }
        float s0 = 0.f, q0 = 0.f, s1 = 0.f, q1 = 0.f;
        #pragma unroll
        for (int nt = 0; nt < 8; nt++) {
            s0 += c[mt][nt][0] + c[mt][nt][1];
            q0 += c[mt][nt][0]*c[mt][nt][0] + c[mt][nt][1]*c[mt][nt][1];
            s1 += c[mt][nt][2] + c[mt][nt][3];
            q1 += c[mt][nt][2]*c[mt][nt][2] + c[mt][nt][3]*c[mt][nt][3];
        }
        s0 += __shfl_xor_sync(0xffffffffu, s0, 1); s0 += __shfl_xor_sync(0xffffffffu, s0, 2);
        q0 += __shfl_xor_sync(0xffffffffu, q0, 1); q0 += __shfl_xor_sync(0xffffffffu, q0, 2);
        s1 += __shfl_xor_sync(0xffffffffu, s1, 1); s1 += __shfl_xor_sync(0xffffffffu, s1, 2);
        q1 += __shfl_xor_sync(0xffffffffu, q1, 1); q1 += __shfl_xor_sync(0xffffffffu, q1, 2);
        if (lm4 == 0) {
            g_p2sum[r0 * B + bimg] = s0;        g_p2sq[r0 * B + bimg] = q0;
            g_p2sum[(r0 + 8) * B + bimg] = s1;  g_p2sq[(r0 + 8) * B + bimg] = q1;
        }
    }

    // ---- tail block: BN2 finalize (same reduction order as old k_bnfin2) ----
    __syncthreads();
    __threadfence();
    if (t == 0) slast = (atomicAdd(&g_ctr2, 1u) == (unsigned)(gridDim.x - 1));
    __syncthreads();
    if (!slast) return;
    if (t == 0) g_ctr2 = 0u;
    for (int ch = warp; ch < C2; ch += 8) {
        const float4* ps = (const float4*)&g_p2sum[ch * B];
        const float4* pq = (const float4*)&g_p2sq [ch * B];
        float s = 0.f, q = 0.f;
        #pragma unroll
        for (int i = 0; i < 4; i++) {
            float4 v = ps[lane * 4 + i]; s += v.x + v.y + v.z + v.w;
            float4 u = pq[lane * 4 + i]; q += u.x + u.y + u.z + u.w;
        }
        #pragma unroll
        for (int o = 16; o; o >>= 1) {
            s += __shfl_xor_sync(0xffffffffu, s, o);
            q += __shfl_xor_sync(0xffffffffu, q, o);
        }
        if (lane == 0) {
            const float invN = 1.0f / (float)(B * 64);
            float mean = s * invN;
            float var  = q * invN - mean * mean;
            float sc = gamma[ch] * rsqrtf(var + BN_EPS);
            g_scale2[ch] = sc;
            g_shift2[ch] = beta[ch] - mean * sc;
        }
    }
}

// ---------------- fc1: fp16 mma (ldmatrix frags), BN2+ReLU fused, BN3 partials ----------
#define FC1_STR 136
__global__ __launch_bounds__(256) void k_fc1() {
    __shared__ __half sA[64 * FC1_STR];
    __shared__ __half sB[64 * FC1_STR];
    const int t = threadIdx.x;
    const int lane = t & 31, warp = t >> 5;
    const int l4 = lane >> 2, lm4 = lane & 3;
    const int wm = warp >> 2, wn = warp & 3;
    const int b0 = blockIdx.x * 64, f0 = blockIdx.y * 64;
    const int m0w = wm * 32, n0w = wn * 16;

    const unsigned sAa = (unsigned)__cvta_generic_to_shared(sA);
    const unsigned sBa = (unsigned)__cvta_generic_to_shared(sB);
    const unsigned aoff = ((m0w + (lane & 15)) * FC1_STR) * 2 + ((lane >> 4) << 4);
    const unsigned boff = ((n0w + (lane & 7)) * FC1_STR) * 2 + (((lane >> 3) & 1) << 4);

    float c[2][2][4];
    #pragma unroll
    for (int i = 0; i < 2; i++)
        #pragma unroll
        for (int j = 0; j < 2; j++)
            #pragma unroll
            for (int r = 0; r < 4; r++) c[i][j][r] = 0.f;

    for (int kc = 0; kc < 16; kc++) {
        if (kc) __syncthreads();
        #pragma unroll
        for (int j = 0; j < 16; j++) {
            int idx = t + 256 * j;
            int bl = idx >> 6, kp = idx & 63;
            int kg = kc * 128 + 2 * kp;
            float2 v = *(const float2*)&g_h1[(b0 + bl) * FLAT + kg];
            int c0 = kg >> 4, c1 = (kg + 1) >> 4;
            float v0 = fmaxf(fmaf(g_scale2[c0], v.x, g_shift2[c0]), 0.0f);
            float v1 = fmaxf(fmaf(g_scale2[c1], v.y, g_shift2[c1]), 0.0f);
            *(__half2*)&sA[bl * FC1_STR + 2 * kp] = __floats2half2_rn(v0, v1);
        }
        #pragma unroll
        for (int j = 0; j < 4; j++) {
            int idx = t + 256 * j;
            int fl = idx >> 4, k8 = idx & 15;
            *(uint4*)&sB[fl * FC1_STR + k8 * 8] =
                *(const uint4*)&g_qf1h[(f0 + fl) * FLAT + kc * 128 + k8 * 8];
        }
        __syncthreads();
        #pragma unroll
        for (int ks = 0; ks < 8; ks++) {
            const unsigned k0b = ks * 32;
            unsigned a[2][4], bf[2][2];
            #pragma unroll
            for (int mt = 0; mt < 2; mt++)
                ldsm4(a[mt][0], a[mt][1], a[mt][2], a[mt][3],
                      sAa + aoff + (unsigned)(mt * 16 * FC1_STR * 2) + k0b);
            #pragma unroll
            for (int nt = 0; nt < 2; nt++)
                ldsm2(bf[nt][0], bf[nt][1],
                      sBa + boff + (unsigned)(nt * 8 * FC1_STR * 2) + k0b);
            #pragma unroll
            for (int mt = 0; mt < 2; mt++)
                #pragma unroll
                for (int nt = 0; nt < 2; nt++)
                    asm volatile(
                        "mma.sync.aligned.m16n8k16.row.col.f32.f16.f16.f32 "
                        "{%0,%1,%2,%3},{%4,%5,%6,%7},{%8,%9},{%0,%1,%2,%3};"
                        : "+f"(c[mt][nt][0]), "+f"(c[mt][nt][1]),
                          "+f"(c[mt][nt][2]), "+f"(c[mt][nt][3])
                        : "r"(a[mt][0]), "r"(a[mt][1]), "r"(a[mt][2]), "r"(a[mt][3]),
                          "r"(bf[nt][0]), "r"(bf[nt][1]));
        }
    }
    #pragma unroll
    for (int mt = 0; mt < 2; mt++) {
        int rA = b0 + m0w + mt * 16 + l4;
        #pragma unroll
        for (int nt = 0; nt < 2; nt++) {
            int cc = f0 + n0w + nt * 8 + 2 * lm4;
            *(float2*)&g_fc1[rA * F1 + cc]       = make_float2(c[mt][nt][0], c[mt][nt][1]);
            *(float2*)&g_fc1[(rA + 8) * F1 + cc] = make_float2(c[mt][nt][2], c[mt][nt][3]);
        }
    }
    __syncthreads();
    float* srs = (float*)sB;
    float* srq = srs + 128;
    #pragma unroll
    for (int nt = 0; nt < 2; nt++) {
        #pragma unroll
        for (int j = 0; j < 2; j++) {
            float s = 0.f, q = 0.f;
            #pragma unroll
            for (int mt = 0; mt < 2; mt++) {
                s += c[mt][nt][j] + c[mt][nt][j + 2];
                q += c[mt][nt][j]*c[mt][nt][j] + c[mt][nt][j+2]*c[mt][nt][j+2];
            }
            #pragma unroll
            for (int o = 4; o < 32; o <<= 1) {
                s += __shfl_xor_sync(0xffffffffu, s, o);
                q += __shfl_xor_sync(0xffffffffu, q, o);
            }
            if (l4 == 0) {
                int fl = n0w + nt * 8 + 2 * lm4 + j;
                srs[wm * 64 + fl] = s;
                srq[wm * 64 + fl] = q;
            }
        }
    }
    __syncthreads();
    if (t < 64) {
        float S = srs[t] + srs[64 + t];
        float Q = srq[t] + srq[64 + t];
        g_p3s[(f0 + t) * 8 + blockIdx.x] = S;
        g_p3q[(f0 + t) * 8 + blockIdx.x] = Q;
    }
}

// ---------------- fc2: BN3 finalize (redundant per block) + bn3+relu+fc2 ----------------
__global__ __launch_bounds__(256) void k_fc2(const float* __restrict__ fc2_b,
                                             const float* __restrict__ bn3_g,
                                             const float* __restrict__ bn3_b,
                                             float* __restrict__ out) {
    __shared__ float swq[F2 * F1];
    __shared__ float sscale[F1], sshift[F1];
    __shared__ float sbias[F2];
    const int t = threadIdx.x;
    for (int i = t; i < F2 * F1; i += 256) swq[i] = g_qf2[i];
    if (t < F2) sbias[t] = fc2_b[t];
    #pragma unroll
    for (int j = 0; j < 2; j++) {
        int f = t + 256 * j;
        float4 sa = *(const float4*)&g_p3s[f * 8];
        float4 sb = *(const float4*)&g_p3s[f * 8 + 4];
        float4 qa = *(const float4*)&g_p3q[f * 8];
        float4 qb = *(const float4*)&g_p3q[f * 8 + 4];
        float S = sa.x + sa.y + sa.z + sa.w + sb.x + sb.y + sb.z + sb.w;
        float Q = qa.x + qa.y + qa.z + qa.w + qb.x + qb.y + qb.z + qb.w;
        const float invN = 1.0f / (float)B;
        float mean = S * invN;
        float var  = Q * invN - mean * mean;
        float sc = bn3_g[f] * rsqrtf(var + BN_EPS);
        sscale[f] = sc;
        sshift[f] = bn3_b[f] - mean * sc;
    }
    __syncthreads();
    const int warp = t >> 5, lane = t & 31;
    const int b = blockIdx.x * 8 + warp;
    float h[16];
    #pragma unroll
    for (int i = 0; i < 16; i++) {
        int f = lane + 32 * i;
        float v = g_fc1[b * F1 + f];
        h[i] = fmaxf(fmaf(sscale[f], v, sshift[f]), 0.0f);
    }
    #pragma unroll
    for (int o = 0; o < F2; o++) {
        float acc = 0.f;
        #pragma unroll
        for (int i = 0; i < 16; i++)
            acc = fmaf(h[i], swq[o * F1 + lane + 32 * i], acc);
        #pragma unroll
        for (int s = 16; s; s >>= 1)
            acc += __shfl_xor_sync(0xffffffffu, acc, s);
        if (lane == 0) out[b * F2 + o] = acc + sbias[o];
    }
}

// ---------------- launcher ----------------
extern "C" void kernel_launch(void* const* d_in, const int* in_sizes, int n_in,
                              void* d_out, int out_size) {
    const float* x       = (const float*)d_in[0];
    const float* conv1_w = (const float*)d_in[1];
    const float* bn1_g   = (const float*)d_in[3];
    const float* bn1_b   = (const float*)d_in[4];
    const float* conv2_w = (const float*)d_in[5];
    const float* bn2_g   = (const float*)d_in[7];
    const float* bn2_b   = (const float*)d_in[8];
    const float* fc1_w   = (const float*)d_in[9];
    const float* bn3_g   = (const float*)d_in[11];
    const float* bn3_b   = (const float*)d_in[12];
    const float* fc2_w   = (const float*)d_in[13];
    const float* fc2_b   = (const float*)d_in[14];
    float* out = (float*)d_out;

    cudaFuncSetAttribute(k_conv1, cudaFuncAttributeMaxDynamicSharedMemorySize, CV1_SMEM_BYTES);
    cudaFuncSetAttribute(k_conv2, cudaFuncAttributeMaxDynamicSharedMemorySize, CV2_SMEM_BYTES);

    // quantization (conv/fc biases dropped: train-mode BN cancels them exactly)
    k_absmax_all<<<dim3(128, 4), 256>>>(conv1_w, conv2_w, fc1_w, fc2_w);
    k_quant_all <<<dim3(128, 4), 256>>>(conv1_w, conv2_w, fc1_w, fc2_w);

    // stage 1 (BN1 finalize fused into conv1 tail block)
    k_conv1<<<B, 256, CV1_SMEM_BYTES>>>(x, bn1_g, bn1_b);

    // stage 2 (BN2 finalize fused into conv2 tail block)
    k_conv2<<<B / 4, 256, CV2_SMEM_BYTES>>>(bn2_g, bn2_b);

    // stage 3 (BN3 stats from fc1 epilogue; finalized inside fc2)
    k_fc1<<<dim3(8, 8), 256>>>();
    k_fc2<<<B / 8, 256>>>(fc2_b, bn3_g, bn3_b, out);
}

// round 8
// speedup vs baseline: 1.2869x; 1.2869x over previous
#include <cuda_runtime.h>
#include <cuda_fp16.h>
#include <cuda_bf16.h>

// ---------------- problem constants ----------------
#define B      512
#define C1     64
#define C2     128
#define FLAT   2048
#define F1     512
#define F2     10
#define BN_EPS 1e-5f

// ---------------- device scratch ----------------
__device__ unsigned g_maxabs[4];                  // zero-init; atomicMax idempotent across replays
__device__ __half g_qw1h[C1 * 32];                // conv1 ternary [oc][k pad 32]
__device__ __half g_qw2h[25 * C2 * C1];           // conv2 ternary [khkw][oc][ci]
__device__ __half g_qf1h[F1 * FLAT];              // fc1 ternary [f][k]
__device__ float  g_qf2[F2 * F1];
__device__ float g_pool1[B * 144 * C1];           // RAW pooled conv1 (pre-BN), [b][pixel][ci]
__device__ float g_p1sum[C1 * B], g_p1sq[C1 * B];
__device__ float g_scale1[C1], g_shift1[C1];
__device__ float g_p2sum[C2 * B], g_p2sq[C2 * B];
__device__ float g_scale2[C2], g_shift2[C2];
__device__ float g_h1[B * FLAT];                  // RAW pooled conv2 (pre-BN)
__device__ float g_fc1[B * F1];                   // RAW fc1 (pre-BN)
__device__ float g_p3s[F1 * 8], g_p3q[F1 * 8];    // BN3 partials: [feature][b-tile]

// ---------------- cp.async helpers ----------------
__device__ __forceinline__ void cp16(__half* smem_dst, const __half* gsrc) {
    unsigned s = (unsigned)__cvta_generic_to_shared(smem_dst);
    asm volatile("cp.async.cg.shared.global [%0], [%1], 16;\n" :: "r"(s), "l"(gsrc));
}
#define CP_COMMIT() asm volatile("cp.async.commit_group;\n" ::: "memory")
#define CP_WAIT0()  asm volatile("cp.async.wait_group 0;\n" ::: "memory")

// ---------------- quantization ----------------
__global__ void k_absmax_all(const float* __restrict__ w0, const float* __restrict__ w1,
                             const float* __restrict__ w2, const float* __restrict__ w3) {
    const int slot = blockIdx.y;
    const float* w = (slot == 0) ? w0 : (slot == 1) ? w1 : (slot == 2) ? w2 : w3;
    const int n4 = ((slot == 0) ? 1600 : (slot == 1) ? 204800 : (slot == 2) ? 1048576 : 5120) >> 2;
    const float4* w4 = (const float4*)w;
    unsigned m = 0u;
    #pragma unroll 4
    for (int i = blockIdx.x * blockDim.x + threadIdx.x; i < n4; i += gridDim.x * blockDim.x) {
        float4 v = w4[i];
        m = max(m, __float_as_uint(fabsf(v.x)));
        m = max(m, __float_as_uint(fabsf(v.y)));
        m = max(m, __float_as_uint(fabsf(v.z)));
        m = max(m, __float_as_uint(fabsf(v.w)));
    }
    #pragma unroll
    for (int o = 16; o; o >>= 1)
        m = max(m, __shfl_xor_sync(0xffffffffu, m, o));
    if ((threadIdx.x & 31) == 0) atomicMax(&g_maxabs[slot], m);
}

__global__ void k_quant_all(const float* __restrict__ w0, const float* __restrict__ w1,
                            const float* __restrict__ w2, const float* __restrict__ w3) {
    const int slot = blockIdx.y;
    const float* w = (slot == 0) ? w0 : (slot == 1) ? w1 : (slot == 2) ? w2 : w3;
    const int n4 = ((slot == 0) ? 1600 : (slot == 1) ? 204800 : (slot == 2) ? 1048576 : 5120) >> 2;
    const float4* w4 = (const float4*)w;
    const float t = 0.05f * __uint_as_float(g_maxabs[slot]);
    #pragma unroll 2
    for (int i = blockIdx.x * blockDim.x + threadIdx.x; i < n4; i += gridDim.x * blockDim.x) {
        float4 v = w4[i];
        float q0 = (v.x > t) ? 1.0f : ((v.x < -t) ? -1.0f : 0.0f);
        float q1 = (v.y > t) ? 1.0f : ((v.y < -t) ? -1.0f : 0.0f);
        float q2 = (v.z > t) ? 1.0f : ((v.z < -t) ? -1.0f : 0.0f);
        float q3 = (v.w > t) ? 1.0f : ((v.w < -t) ? -1.0f : 0.0f);
        int base = 4 * i;
        if (slot == 0) {
            float qs[4] = {q0, q1, q2, q3};
            #pragma unroll
            for (int u = 0; u < 4; u++) {
                int idx = base + u, oc = idx / 25, k = idx - oc * 25;
                g_qw1h[oc * 32 + k] = __float2half(qs[u]);
            }
        } else if (slot == 1) {
            float qs[4] = {q0, q1, q2, q3};
            #pragma unroll
            for (int u = 0; u < 4; u++) {
                int idx = base + u;
                int oc = idx / 1600, rem = idx - oc * 1600, ci = rem / 25, kk = rem - ci * 25;
                g_qw2h[kk * (C2 * C1) + oc * C1 + ci] = __float2half(qs[u]);
            }
        } else if (slot == 2) {
            *(__half2*)&g_qf1h[base]     = __floats2half2_rn(q0, q1);
            *(__half2*)&g_qf1h[base + 2] = __floats2half2_rn(q2, q3);
        } else {
            *(float4*)&g_qf2[base] = make_float4(q0, q1, q2, q3);
        }
    }
}

// ---------------- conv1: fp16 mma, pool-window-major N ------
#define CV1_SMEM_BYTES (3136 + 5120 + 46080)
__global__ __launch_bounds__(256) void k_conv1(const float* __restrict__ x) {
    extern __shared__ char c1sm[];
    float*  sxf = (float*)c1sm;
    __half* sA  = (__half*)(c1sm + 3136);
    __half* sB  = (__half*)(c1sm + 3136 + 5120);
    __shared__ float srs[64][9], srq[64][9];
    const int b = blockIdx.x, t = threadIdx.x;
    const int lane = t & 31, warp = t >> 5;
    const int l4 = lane >> 2, lm4 = lane & 3;

    for (int i = t; i < 784; i += 256) sxf[i] = x[b * 784 + i];
    #pragma unroll
    for (int j = 0; j < 2; j++) {
        int i = t + 256 * j;
        int oc = i >> 3, c4 = i & 7;
        *(uint2*)&sA[oc * 40 + c4 * 4] = *(const uint2*)&g_qw1h[oc * 32 + c4 * 4];
    }
    __syncthreads();

    {
        const int kp = t & 15, n0 = t >> 4;
        const int k0 = 2 * kp;
        const int kh0 = k0 / 5, kw0 = k0 - 5 * kh0;
        const int kh1 = (k0 + 1) / 5, kw1 = (k0 + 1) - 5 * kh1;
        const bool e0 = (k0 < 25), e1 = (k0 + 1 < 25);
        #pragma unroll 4
        for (int st = 0; st < 36; st++) {
            int n = n0 + 16 * st;
            int w = n >> 2, j = n & 3;
            int py = w / 12, px = w - 12 * py;
            int iy = 2 * py + (j >> 1), ix = 2 * px + (j & 1);
            float v0 = e0 ? sxf[(iy + kh0) * 28 + ix + kw0] : 0.f;
            float v1 = e1 ? sxf[(iy + kh1) * 28 + ix + kw1] : 0.f;
            *(__half2*)&sB[n * 40 + k0] = __floats2half2_rn(v0, v1);
        }
    }
    __syncthreads();

    unsigned a[4][2][4];
    #pragma unroll
    for (int mt = 0; mt < 4; mt++) {
        const __half* ap = sA + (mt * 16 + l4) * 40 + 2 * lm4;
        #pragma unroll
        for (int ks = 0; ks < 2; ks++) {
            a[mt][ks][0] = *(const unsigned*)(ap + 16 * ks);
            a[mt][ks][1] = *(const unsigned*)(ap + 16 * ks + 8 * 40);
            a[mt][ks][2] = *(const unsigned*)(ap + 16 * ks + 8);
            a[mt][ks][3] = *(const unsigned*)(ap + 16 * ks + 8 * 40 + 8);
        }
    }

    float s0a[4] = {0,0,0,0}, s1a[4] = {0,0,0,0};
    float q0a[4] = {0,0,0,0}, q1a[4] = {0,0,0,0};

    #pragma unroll
    for (int nt = 0; nt < 9; nt++) {
        const __half* bp = sB + (warp * 72 + nt * 8 + l4) * 40 + 2 * lm4;
        unsigned bf[2][2];
        #pragma unroll
        for (int ks = 0; ks < 2; ks++) {
            bf[ks][0] = *(const unsigned*)(bp + 16 * ks);
            bf[ks][1] = *(const unsigned*)(bp + 16 * ks + 8);
        }
        float c[4][4];
        #pragma unroll
        for (int mt = 0; mt < 4; mt++) {
            c[mt][0] = c[mt][1] = c[mt][2] = c[mt][3] = 0.f;
            #pragma unroll
            for (int ks = 0; ks < 2; ks++)
                asm volatile(
                    "mma.sync.aligned.m16n8k16.row.col.f32.f16.f16.f32 "
                    "{%0,%1,%2,%3},{%4,%5,%6,%7},{%8,%9},{%0,%1,%2,%3};"
                    : "+f"(c[mt][0]), "+f"(c[mt][1]), "+f"(c[mt][2]), "+f"(c[mt][3])
                    : "r"(a[mt][ks][0]), "r"(a[mt][ks][1]), "r"(a[mt][ks][2]), "r"(a[mt][ks][3]),
                      "r"(bf[ks][0]), "r"(bf[ks][1]));
        }
        const int wdw = warp * 18 + nt * 2 + (lm4 >> 1);
        #pragma unroll
        for (int mt = 0; mt < 4; mt++) {
            s0a[mt] += c[mt][0] + c[mt][1];
            q0a[mt] += c[mt][0]*c[mt][0] + c[mt][1]*c[mt][1];
            s1a[mt] += c[mt][2] + c[mt][3];
            q1a[mt] += c[mt][2]*c[mt][2] + c[mt][3]*c[mt][3];
            float m0 = fmaxf(c[mt][0], c[mt][1]);
            float m1 = fmaxf(c[mt][2], c[mt][3]);
            m0 = fmaxf(m0, __shfl_xor_sync(0xffffffffu, m0, 1));
            m1 = fmaxf(m1, __shfl_xor_sync(0xffffffffu, m1, 1));
            if ((lm4 & 1) == 0) {
                int oc = mt * 16 + l4;
                g_pool1[b * 9216 + wdw * 64 + oc]     = m0;
                g_pool1[b * 9216 + wdw * 64 + oc + 8] = m1;
            }
        }
    }

    #pragma unroll
    for (int mt = 0; mt < 4; mt++) {
        float s0 = s0a[mt], q0 = q0a[mt], s1 = s1a[mt], q1 = q1a[mt];
        s0 += __shfl_xor_sync(0xffffffffu, s0, 1); s0 += __shfl_xor_sync(0xffffffffu, s0, 2);
        q0 += __shfl_xor_sync(0xffffffffu, q0, 1); q0 += __shfl_xor_sync(0xffffffffu, q0, 2);
        s1 += __shfl_xor_sync(0xffffffffu, s1, 1); s1 += __shfl_xor_sync(0xffffffffu, s1, 2);
        q1 += __shfl_xor_sync(0xffffffffu, q1, 1); q1 += __shfl_xor_sync(0xffffffffu, q1, 2);
        if (lm4 == 0) {
            srs[mt * 16 + l4][warp] = s0;     srq[mt * 16 + l4][warp] = q0;
            srs[mt * 16 + l4 + 8][warp] = s1; srq[mt * 16 + l4 + 8][warp] = q1;
        }
    }
    __syncthreads();
    if (t < 64) {
        float S = 0.f, Q = 0.f;
        #pragma unroll
        for (int w = 0; w < 8; w++) { S += srs[t][w]; Q += srq[t][w]; }
        g_p1sum[t * B + b] = S;
        g_p1sq [t * B + b] = Q;
    }
}

// ---------------- BN finalize: warp-per-channel, shfl-only ----------------
__global__ void k_bnfin1(const float* __restrict__ gamma, const float* __restrict__ beta) {
    const int w = threadIdx.x >> 5, lane = threadIdx.x & 31;
    const int c = blockIdx.x * 8 + w;
    const float4* ps = (const float4*)&g_p1sum[c * B];
    const float4* pq = (const float4*)&g_p1sq [c * B];
    float s = 0.f, q = 0.f;
    #pragma unroll
    for (int i = 0; i < 4; i++) {
        float4 v = ps[lane * 4 + i]; s += v.x + v.y + v.z + v.w;
        float4 u = pq[lane * 4 + i]; q += u.x + u.y + u.z + u.w;
    }
    #pragma unroll
    for (int o = 16; o; o >>= 1) {
        s += __shfl_xor_sync(0xffffffffu, s, o);
        q += __shfl_xor_sync(0xffffffffu, q, o);
    }
    if (lane == 0) {
        const float invN = 1.0f / (float)(B * 576);
        float mean = s * invN;
        float var  = q * invN - mean * mean;
        float sc = gamma[c] * rsqrtf(var + BN_EPS);
        g_scale1[c] = sc;
        g_shift1[c] = beta[c] - mean * sc;
    }
}

__global__ void k_bnfin2(const float* __restrict__ gamma, const float* __restrict__ beta) {
    const int w = threadIdx.x >> 5, lane = threadIdx.x & 31;
    const int c = blockIdx.x * 8 + w;
    const float4* ps = (const float4*)&g_p2sum[c * B];
    const float4* pq = (const float4*)&g_p2sq [c * B];
    float s = 0.f, q = 0.f;
    #pragma unroll
    for (int i = 0; i < 4; i++) {
        float4 v = ps[lane * 4 + i]; s += v.x + v.y + v.z + v.w;
        float4 u = pq[lane * 4 + i]; q += u.x + u.y + u.z + u.w;
    }
    #pragma unroll
    for (int o = 16; o; o >>= 1) {
        s += __shfl_xor_sync(0xffffffffu, s, o);
        q += __shfl_xor_sync(0xffffffffu, q, o);
    }
    if (lane == 0) {
        const float invN = 1.0f / (float)(B * 64);
        float mean = s * invN;
        float var  = q * invN - mean * mean;
        float sc = gamma[c] * rsqrtf(var + BN_EPS);
        g_scale2[c] = sc;
        g_shift2[c] = beta[c] - mean * sc;
    }
}

// ---------------- conv2: fp16 mma implicit GEMM, 4 images/block, 512 threads ------------
// 16 warps: wm(4) x wn(4 images); warp = 32 oc x 64 px. Same math order as before
// (each output's k-accumulation order unchanged) -> bit-identical results.
#define CV2_CSTR 72
#define CV2_IMGH (144 * CV2_CSTR)
#define CV2_SA_H (4 * CV2_IMGH)
#define CV2_WBUF (C2 * CV2_CSTR)
#define CV2_SMEM_BYTES ((CV2_SA_H + 2 * CV2_WBUF) * 2)

__global__ __launch_bounds__(512, 1) void k_conv2() {
    extern __shared__ __half smh[];
    __half* sxh = smh;
    __half* sA0 = smh + CV2_SA_H;
    __half* sA1 = sA0 + CV2_WBUF;
    const int b4 = blockIdx.x * 4;
    const int t = threadIdx.x;
    const int lane = t & 31, warp = t >> 5;
    const int l4 = lane >> 2, lm4 = lane & 3;
    const int wm = warp >> 2, wn = warp & 3;
    const int m0w = wm * 32;

    {
        const __half* wsrc = g_qw2h;
        #pragma unroll
        for (int j = 0; j < 2; j++) {
            int idx = t + 512 * j;
            int oc = idx >> 3, c8 = idx & 7;
            cp16(sA0 + oc * CV2_CSTR + c8 * 8, wsrc + idx * 8);
        }
        CP_COMMIT();
    }

    for (int idx = t; idx < 4 * 144 * 32; idx += 512) {
        int img = idx / 4608, r = idx - img * 4608;
        int p = r >> 5, cp = r & 31;
        int ci0 = 2 * cp;
        float2 v = *(const float2*)&g_pool1[(b4 + img) * 9216 + p * 64 + ci0];
        float v0 = fmaxf(fmaf(g_scale1[ci0],     v.x, g_shift1[ci0]),     0.0f);
        float v1 = fmaxf(fmaf(g_scale1[ci0 + 1], v.y, g_shift1[ci0 + 1]), 0.0f);
        *(__half2*)&sxh[img * CV2_IMGH + p * CV2_CSTR + ci0] = __floats2half2_rn(v0, v1);
    }

    float c[2][8][4];
    #pragma unroll
    for (int i = 0; i < 2; i++)
        #pragma unroll
        for (int j = 0; j < 8; j++)
            #pragma unroll
            for (int r = 0; r < 4; r++) c[i][j][r] = 0.f;

    for (int khkw = 0; khkw < 25; khkw++) {
        const __half* sA = (khkw & 1) ? sA1 : sA0;
        CP_WAIT0();
        __syncthreads();
        if (khkw < 24) {
            __half* dst = (khkw & 1) ? sA0 : sA1;
            const __half* wsrc = g_qw2h + (khkw + 1) * (C2 * C1);
            #pragma unroll
            for (int j = 0; j < 2; j++) {
                int idx = t + 512 * j;
                int oc = idx >> 3, c8 = idx & 7;
                cp16(dst + oc * CV2_CSTR + c8 * 8, wsrc + idx * 8);
            }
            CP_COMMIT();
        }
        const int kh = khkw / 5, kw = khkw - 5 * kh;
        const __half* bbase = sxh + wn * CV2_IMGH
                            + (kh * 12 + kw + l4) * CV2_CSTR + 2 * lm4;
        #pragma unroll
        for (int ks = 0; ks < 4; ks++) {
            const int k0 = ks * 16;
            unsigned a[2][4], bf[8][2];
            #pragma unroll
            for (int mt = 0; mt < 2; mt++) {
                const __half* ap = sA + (m0w + mt * 16 + l4) * CV2_CSTR + k0 + 2 * lm4;
                a[mt][0] = *(const unsigned*)(ap);
                a[mt][1] = *(const unsigned*)(ap + 8 * CV2_CSTR);
                a[mt][2] = *(const unsigned*)(ap + 8);
                a[mt][3] = *(const unsigned*)(ap + 8 * CV2_CSTR + 8);
            }
            const __half* bp = bbase + k0;
            #pragma unroll
            for (int nt = 0; nt < 8; nt++) {
                bf[nt][0] = *(const unsigned*)(bp + nt * 12 * CV2_CSTR);
                bf[nt][1] = *(const unsigned*)(bp + nt * 12 * CV2_CSTR + 8);
            }
            #pragma unroll
            for (int mt = 0; mt < 2; mt++)
                #pragma unroll
                for (int nt = 0; nt < 8; nt++)
                    asm volatile(
                        "mma.sync.aligned.m16n8k16.row.col.f32.f16.f16.f32 "
                        "{%0,%1,%2,%3},{%4,%5,%6,%7},{%8,%9},{%0,%1,%2,%3};"
                        : "+f"(c[mt][nt][0]), "+f"(c[mt][nt][1]),
                          "+f"(c[mt][nt][2]), "+f"(c[mt][nt][3])
                        : "r"(a[mt][0]), "r"(a[mt][1]), "r"(a[mt][2]), "r"(a[mt][3]),
                          "r"(bf[nt][0]), "r"(bf[nt][1]));
        }
    }

    const int bimg = b4 + wn;
    #pragma unroll
    for (int mt = 0; mt < 2; mt++) {
        int r0 = m0w + mt * 16 + l4;
        #pragma unroll
        for (int tp = 0; tp < 4; tp++) {
            float pA = fmaxf(fmaxf(c[mt][2*tp][0], c[mt][2*tp][1]),
                             fmaxf(c[mt][2*tp+1][0], c[mt][2*tp+1][1]));
            float pB = fmaxf(fmaxf(c[mt][2*tp][2], c[mt][2*tp][3]),
                             fmaxf(c[mt][2*tp+1][2], c[mt][2*tp+1][3]));
            g_h1[bimg * FLAT + r0 * 16 + tp * 4 + lm4] = pA;
            g_h1[bimg * FLAT + (r0 + 8) * 16 + tp * 4 + lm4] = pB;
        }
        float s0 = 0.f, q0 = 0.f, s1 = 0.f, q1 = 0.f;
        #pragma unroll
        for (int nt = 0; nt < 8; nt++) {
            s0 += c[mt][nt][0] + c[mt][nt][1];
            q0 += c[mt][nt][0]*c[mt][nt][0] + c[mt][nt][1]*c[mt][nt][1];
            s1 += c[mt][nt][2] + c[mt][nt][3];
            q1 += c[mt][nt][2]*c[mt][nt][2] + c[mt][nt][3]*c[mt][nt][3];
        }
        s0 += __shfl_xor_sync(0xffffffffu, s0, 1); s0 += __shfl_xor_sync(0xffffffffu, s0, 2);
        q0 += __shfl_xor_sync(0xffffffffu, q0, 1); q0 += __shfl_xor_sync(0xffffffffu, q0, 2);
        s1 += __shfl_xor_sync(0xffffffffu, s1, 1); s1 += __shfl_xor_sync(0xffffffffu, s1, 2);
        q1 += __shfl_xor_sync(0xffffffffu, q1, 1); q1 += __shfl_xor_sync(0xffffffffu, q1, 2);
        if (lm4 == 0) {
            g_p2sum[r0 * B + bimg] = s0;        g_p2sq[r0 * B + bimg] = q0;
            g_p2sum[(r0 + 8) * B + bimg] = s1;  g_p2sq[(r0 + 8) * B + bimg] = q1;
        }
    }
}

// ---------------- fc1: fp16 mma, k-chunk 128, BN2+ReLU fused, BN3 partials in epilogue --
#define FC1_STR 136
__global__ __launch_bounds__(256) void k_fc1() {
    __shared__ __half sA[64 * FC1_STR];
    __shared__ __half sB[64 * FC1_STR];
    const int t = threadIdx.x;
    const int lane = t & 31, warp = t >> 5;
    const int l4 = lane >> 2, lm4 = lane & 3;
    const int wm = warp >> 2, wn = warp & 3;
    const int b0 = blockIdx.x * 64, f0 = blockIdx.y * 64;
    const int m0w = wm * 32, n0w = wn * 16;

    float c[2][2][4];
    #pragma unroll
    for (int i = 0; i < 2; i++)
        #pragma unroll
        for (int j = 0; j < 2; j++)
            #pragma unroll
            for (int r = 0; r < 4; r++) c[i][j][r] = 0.f;

    for (int kc = 0; kc < 16; kc++) {
        if (kc) __syncthreads();
        #pragma unroll
        for (int j = 0; j < 16; j++) {
            int idx = t + 256 * j;
            int bl = idx >> 6, kp = idx & 63;
            int kg = kc * 128 + 2 * kp;
            float2 v = *(const float2*)&g_h1[(b0 + bl) * FLAT + kg];
            int c0 = kg >> 4, c1 = (kg + 1) >> 4;
            float v0 = fmaxf(fmaf(g_scale2[c0], v.x, g_shift2[c0]), 0.0f);
            float v1 = fmaxf(fmaf(g_scale2[c1], v.y, g_shift2[c1]), 0.0f);
            *(__half2*)&sA[bl * FC1_STR + 2 * kp] = __floats2half2_rn(v0, v1);
        }
        #pragma unroll
        for (int j = 0; j < 4; j++) {
            int idx = t + 256 * j;
            int fl = idx >> 4, k8 = idx & 15;
            *(uint4*)&sB[fl * FC1_STR + k8 * 8] =
                *(const uint4*)&g_qf1h[(f0 + fl) * FLAT + kc * 128 + k8 * 8];
        }
        __syncthreads();
        #pragma unroll
        for (int ks = 0; ks < 8; ks++) {
            const int k0 = ks * 16;
            unsigned a[2][4], bf[2][2];
            #pragma unroll
            for (int mt = 0; mt < 2; mt++) {
                const __half* ap = sA + (m0w + mt * 16 + l4) * FC1_STR + k0 + 2 * lm4;
                a[mt][0] = *(const unsigned*)(ap);
                a[mt][1] = *(const unsigned*)(ap + 8 * FC1_STR);
                a[mt][2] = *(const unsigned*)(ap + 8);
                a[mt][3] = *(const unsigned*)(ap + 8 * FC1_STR + 8);
            }
            #pragma unroll
            for (int nt = 0; nt < 2; nt++) {
                const __half* bp = sB + (n0w + nt * 8 + l4) * FC1_STR + k0 + 2 * lm4;
                bf[nt][0] = *(const unsigned*)(bp);
                bf[nt][1] = *(const unsigned*)(bp + 8);
            }
            #pragma unroll
            for (int mt = 0; mt < 2; mt++)
                #pragma unroll
                for (int nt = 0; nt < 2; nt++)
                    asm volatile(
                        "mma.sync.aligned.m16n8k16.row.col.f32.f16.f16.f32 "
                        "{%0,%1,%2,%3},{%4,%5,%6,%7},{%8,%9},{%0,%1,%2,%3};"
                        : "+f"(c[mt][nt][0]), "+f"(c[mt][nt][1]),
                          "+f"(c[mt][nt][2]), "+f"(c[mt][nt][3])
                        : "r"(a[mt][0]), "r"(a[mt][1]), "r"(a[mt][2]), "r"(a[mt][3]),
                          "r"(bf[nt][0]), "r"(bf[nt][1]));
        }
    }
    #pragma unroll
    for (int mt = 0; mt < 2; mt++) {
        int rA = b0 + m0w + mt * 16 + l4;
        #pragma unroll
        for (int nt = 0; nt < 2; nt++) {
            int cc = f0 + n0w + nt * 8 + 2 * lm4;
            *(float2*)&g_fc1[rA * F1 + cc]       = make_float2(c[mt][nt][0], c[mt][nt][1]);
            *(float2*)&g_fc1[(rA + 8) * F1 + cc] = make_float2(c[mt][nt][2], c[mt][nt][3]);
        }
    }
    __syncthreads();
    float* srs = (float*)sB;
    float* srq = srs + 128;
    #pragma unroll
    for (int nt = 0; nt < 2; nt++) {
        #pragma unroll
        for (int j = 0; j < 2; j++) {
            float s = 0.f, q = 0.f;
            #pragma unroll
            for (int mt = 0; mt < 2; mt++) {
                s += c[mt][nt][j] + c[mt][nt][j + 2];
                q += c[mt][nt][j]*c[mt][nt][j] + c[mt][nt][j+2]*c[mt][nt][j+2];
            }
            #pragma unroll
            for (int o = 4; o < 32; o <<= 1) {
                s += __shfl_xor_sync(0xffffffffu, s, o);
                q += __shfl_xor_sync(0xffffffffu, q, o);
            }
            if (l4 == 0) {
                int fl = n0w + nt * 8 + 2 * lm4 + j;
                srs[wm * 64 + fl] = s;
                srq[wm * 64 + fl] = q;
            }
        }
    }
    __syncthreads();
    if (t < 64) {
        float S = srs[t] + srs[64 + t];
        float Q = srq[t] + srq[64 + t];
        g_p3s[(f0 + t) * 8 + blockIdx.x] = S;
        g_p3q[(f0 + t) * 8 + blockIdx.x] = Q;
    }
}

// ---------------- fc2: BN3 finalize (redundant per block) + bn3+relu+fc2 ----------------
__global__ __launch_bounds__(256) void k_fc2(const float* __restrict__ fc2_b,
                                             const float* __restrict__ bn3_g,
                                             const float* __restrict__ bn3_b,
                                             float* __restrict__ out) {
    __shared__ float swq[F2 * F1];
    __shared__ float sscale[F1], sshift[F1];
    __shared__ float sbias[F2];
    const int t = threadIdx.x;
    for (int i = t; i < F2 * F1; i += 256) swq[i] = g_qf2[i];
    if (t < F2) sbias[t] = fc2_b[t];
    #pragma unroll
    for (int j = 0; j < 2; j++) {
        int f = t + 256 * j;
        float4 sa = *(const float4*)&g_p3s[f * 8];
        float4 sb = *(const float4*)&g_p3s[f * 8 + 4];
        float4 qa = *(const float4*)&g_p3q[f * 8];
        float4 qb = *(const float4*)&g_p3q[f * 8 + 4];
        float S = sa.x + sa.y + sa.z + sa.w + sb.x + sb.y + sb.z + sb.w;
        float Q = qa.x + qa.y + qa.z + qa.w + qb.x + qb.y + qb.z + qb.w;
        const float invN = 1.0f / (float)B;
        float mean = S * invN;
        float var  = Q * invN - mean * mean;
        float sc = bn3_g[f] * rsqrtf(var + BN_EPS);
        sscale[f] = sc;
        sshift[f] = bn3_b[f] - mean * sc;
    }
    __syncthreads();
    const int warp = t >> 5, lane = t & 31;
    const int b = blockIdx.x * 8 + warp;
    float h[16];
    #pragma unroll
    for (int i = 0; i < 16; i++) {
        int f = lane + 32 * i;
        float v = g_fc1[b * F1 + f];
        h[i] = fmaxf(fmaf(sscale[f], v, sshift[f]), 0.0f);
    }
    #pragma unroll
    for (int o = 0; o < F2; o++) {
        float acc = 0.f;
        #pragma unroll
        for (int i = 0; i < 16; i++)
            acc = fmaf(h[i], swq[o * F1 + lane + 32 * i], acc);
        #pragma unroll
        for (int s = 16; s; s >>= 1)
            acc += __shfl_xor_sync(0xffffffffu, acc, s);
        if (lane == 0) out[b * F2 + o] = acc + sbias[o];
    }
}

// ---------------- launcher ----------------
extern "C" void kernel_launch(void* const* d_in, const int* in_sizes, int n_in,
                              void* d_out, int out_size) {
    const float* x       = (const float*)d_in[0];
    const float* conv1_w = (const float*)d_in[1];
    const float* bn1_g   = (const float*)d_in[3];
    const float* bn1_b   = (const float*)d_in[4];
    const float* conv2_w = (const float*)d_in[5];
    const float* bn2_g   = (const float*)d_in[7];
    const float* bn2_b   = (const float*)d_in[8];
    const float* fc1_w   = (const float*)d_in[9];
    const float* bn3_g   = (const float*)d_in[11];
    const float* bn3_b   = (const float*)d_in[12];
    const float* fc2_w   = (const float*)d_in[13];
    const float* fc2_b   = (const float*)d_in[14];
    float* out = (float*)d_out;

    cudaFuncSetAttribute(k_conv1, cudaFuncAttributeMaxDynamicSharedMemorySize, CV1_SMEM_BYTES);
    cudaFuncSetAttribute(k_conv2, cudaFuncAttributeMaxDynamicSharedMemorySize, CV2_SMEM_BYTES);

    // quantization (conv/fc biases dropped: train-mode BN cancels them exactly)
    k_absmax_all<<<dim3(128, 4), 256>>>(conv1_w, conv2_w, fc1_w, fc2_w);
    k_quant_all <<<dim3(128, 4), 256>>>(conv1_w, conv2_w, fc1_w, fc2_w);

    // stage 1
    k_conv1<<<B, 256, CV1_SMEM_BYTES>>>(x);
    k_bnfin1<<<8, 256>>>(bn1_g, bn1_b);

    // stage 2 (512 threads: 16 warps to hide mma/LDS latency)
    k_conv2<<<B / 4, 512, CV2_SMEM_BYTES>>>();
    k_bnfin2<<<16, 256>>>(bn2_g, bn2_b);

    // stage 3 (BN3 stats from fc1 epilogue; finalized inside fc2)
    k_fc1<<<dim3(8, 8), 256>>>();
    k_fc2<<<B / 8, 256>>>(fc2_b, bn3_g, bn3_b, out);
}

// round 10
// speedup vs baseline: 1.3072x; 1.0158x over previous
#include <cuda_runtime.h>
#include <cuda_fp16.h>
#include <cuda_bf16.h>

// ---------------- problem constants ----------------
#define B      512
#define C1     64
#define C2     128
#define FLAT   2048
#define F1     512
#define F2     10
#define BN_EPS 1e-5f

// ---------------- device scratch ----------------
__device__ unsigned g_maxabs[4];                  // zero-init; atomicMax idempotent across replays
__device__ __half g_qw1h[C1 * 32];                // conv1 ternary [oc][k pad 32]
__device__ __half g_qw2h[25 * C2 * C1];           // conv2 ternary [khkw][oc][ci]
__device__ __half g_qf1h[F1 * FLAT];              // fc1 ternary [f][k]
__device__ float  g_qf2[F2 * F1];
__device__ float g_pool1[B * 144 * C1];           // RAW pooled conv1 (pre-BN), [b][pixel][ci]
__device__ float g_p1sum[C1 * B], g_p1sq[C1 * B];
__device__ float g_scale1[C1], g_shift1[C1];
__device__ float g_p2sum[C2 * B], g_p2sq[C2 * B];
__device__ float g_scale2[C2], g_shift2[C2];
__device__ float g_h1[B * FLAT];                  // RAW pooled conv2 (pre-BN)
__device__ float g_fc1[B * F1];                   // RAW fc1 (pre-BN)
__device__ float g_p3s[F1 * 16], g_p3q[F1 * 16];  // BN3 partials: [feature][b-tile]

// ---------------- cp.async helpers ----------------
__device__ __forceinline__ void cp16(__half* smem_dst, const __half* gsrc) {
    unsigned s = (unsigned)__cvta_generic_to_shared(smem_dst);
    asm volatile("cp.async.cg.shared.global [%0], [%1], 16;\n" :: "r"(s), "l"(gsrc));
}
#define CP_COMMIT() asm volatile("cp.async.commit_group;\n" ::: "memory")
#define CP_WAIT0()  asm volatile("cp.async.wait_group 0;\n" ::: "memory")

// ---------------- quantization ----------------
__global__ void k_absmax_all(const float* __restrict__ w0, const float* __restrict__ w1,
                             const float* __restrict__ w2, const float* __restrict__ w3) {
    const int slot = blockIdx.y;
    const float* w = (slot == 0) ? w0 : (slot == 1) ? w1 : (slot == 2) ? w2 : w3;
    const int n4 = ((slot == 0) ? 1600 : (slot == 1) ? 204800 : (slot == 2) ? 1048576 : 5120) >> 2;
    const float4* w4 = (const float4*)w;
    unsigned m = 0u;
    #pragma unroll 4
    for (int i = blockIdx.x * blockDim.x + threadIdx.x; i < n4; i += gridDim.x * blockDim.x) {
        float4 v = w4[i];
        m = max(m, __float_as_uint(fabsf(v.x)));
        m = max(m, __float_as_uint(fabsf(v.y)));
        m = max(m, __float_as_uint(fabsf(v.z)));
        m = max(m, __float_as_uint(fabsf(v.w)));
    }
    #pragma unroll
    for (int o = 16; o; o >>= 1)
        m = max(m, __shfl_xor_sync(0xffffffffu, m, o));
    if ((threadIdx.x & 31) == 0) atomicMax(&g_maxabs[slot], m);
}

__global__ void k_quant_all(const float* __restrict__ w0, const float* __restrict__ w1,
                            const float* __restrict__ w2, const float* __restrict__ w3) {
    const int slot = blockIdx.y;
    const float* w = (slot == 0) ? w0 : (slot == 1) ? w1 : (slot == 2) ? w2 : w3;
    const int n4 = ((slot == 0) ? 1600 : (slot == 1) ? 204800 : (slot == 2) ? 1048576 : 5120) >> 2;
    const float4* w4 = (const float4*)w;
    const float t = 0.05f * __uint_as_float(g_maxabs[slot]);
    #pragma unroll 2
    for (int i = blockIdx.x * blockDim.x + threadIdx.x; i < n4; i += gridDim.x * blockDim.x) {
        float4 v = w4[i];
        float q0 = (v.x > t) ? 1.0f : ((v.x < -t) ? -1.0f : 0.0f);
        float q1 = (v.y > t) ? 1.0f : ((v.y < -t) ? -1.0f : 0.0f);
        float q2 = (v.z > t) ? 1.0f : ((v.z < -t) ? -1.0f : 0.0f);
        float q3 = (v.w > t) ? 1.0f : ((v.w < -t) ? -1.0f : 0.0f);
        int base = 4 * i;
        if (slot == 0) {
            float qs[4] = {q0, q1, q2, q3};
            #pragma unroll
            for (int u = 0; u < 4; u++) {
                int idx = base + u, oc = idx / 25, k = idx - oc * 25;
                g_qw1h[oc * 32 + k] = __float2half(qs[u]);
            }
        } else if (slot == 1) {
            float qs[4] = {q0, q1, q2, q3};
            #pragma unroll
            for (int u = 0; u < 4; u++) {
                int idx = base + u;
                int oc = idx / 1600, rem = idx - oc * 1600, ci = rem / 25, kk = rem - ci * 25;
                g_qw2h[kk * (C2 * C1) + oc * C1 + ci] = __float2half(qs[u]);
            }
        } else if (slot == 2) {
            *(__half2*)&g_qf1h[base]     = __floats2half2_rn(q0, q1);
            *(__half2*)&g_qf1h[base + 2] = __floats2half2_rn(q2, q3);
        } else {
            *(float4*)&g_qf2[base] = make_float4(q0, q1, q2, q3);
        }
    }
}

// ---------------- conv1: fp16 mma, pool-window-major N ------
#define CV1_SMEM_BYTES (3136 + 5120 + 46080)
__global__ __launch_bounds__(256) void k_conv1(const float* __restrict__ x) {
    extern __shared__ char c1sm[];
    float*  sxf = (float*)c1sm;
    __half* sA  = (__half*)(c1sm + 3136);
    __half* sB  = (__half*)(c1sm + 3136 + 5120);
    __shared__ float srs[64][9], srq[64][9];
    const int b = blockIdx.x, t = threadIdx.x;
    const int lane = t & 31, warp = t >> 5;
    const int l4 = lane >> 2, lm4 = lane & 3;

    for (int i = t; i < 784; i += 256) sxf[i] = x[b * 784 + i];
    #pragma unroll
    for (int j = 0; j < 2; j++) {
        int i = t + 256 * j;
        int oc = i >> 3, c4 = i & 7;
        *(uint2*)&sA[oc * 40 + c4 * 4] = *(const uint2*)&g_qw1h[oc * 32 + c4 * 4];
    }
    __syncthreads();

    {
        const int kp = t & 15, n0 = t >> 4;
        const int k0 = 2 * kp;
        const int kh0 = k0 / 5, kw0 = k0 - 5 * kh0;
        const int kh1 = (k0 + 1) / 5, kw1 = (k0 + 1) - 5 * kh1;
        const bool e0 = (k0 < 25), e1 = (k0 + 1 < 25);
        #pragma unroll 4
        for (int st = 0; st < 36; st++) {
            int n = n0 + 16 * st;
            int w = n >> 2, j = n & 3;
            int py = w / 12, px = w - 12 * py;
            int iy = 2 * py + (j >> 1), ix = 2 * px + (j & 1);
            float v0 = e0 ? sxf[(iy + kh0) * 28 + ix + kw0] : 0.f;
            float v1 = e1 ? sxf[(iy + kh1) * 28 + ix + kw1] : 0.f;
            *(__half2*)&sB[n * 40 + k0] = __floats2half2_rn(v0, v1);
        }
    }
    __syncthreads();

    unsigned a[4][2][4];
    #pragma unroll
    for (int mt = 0; mt < 4; mt++) {
        const __half* ap = sA + (mt * 16 + l4) * 40 + 2 * lm4;
        #pragma unroll
        for (int ks = 0; ks < 2; ks++) {
            a[mt][ks][0] = *(const unsigned*)(ap + 16 * ks);
            a[mt][ks][1] = *(const unsigned*)(ap + 16 * ks + 8 * 40);
            a[mt][ks][2] = *(const unsigned*)(ap + 16 * ks + 8);
            a[mt][ks][3] = *(const unsigned*)(ap + 16 * ks + 8 * 40 + 8);
        }
    }

    float s0a[4] = {0,0,0,0}, s1a[4] = {0,0,0,0};
    float q0a[4] = {0,0,0,0}, q1a[4] = {0,0,0,0};

    #pragma unroll
    for (int nt = 0; nt < 9; nt++) {
        const __half* bp = sB + (warp * 72 + nt * 8 + l4) * 40 + 2 * lm4;
        unsigned bf[2][2];
        #pragma unroll
        for (int ks = 0; ks < 2; ks++) {
            bf[ks][0] = *(const unsigned*)(bp + 16 * ks);
            bf[ks][1] = *(const unsigned*)(bp + 16 * ks + 8);
        }
        float c[4][4];
        #pragma unroll
        for (int mt = 0; mt < 4; mt++) {
            c[mt][0] = c[mt][1] = c[mt][2] = c[mt][3] = 0.f;
            #pragma unroll
            for (int ks = 0; ks < 2; ks++)
                asm volatile(
                    "mma.sync.aligned.m16n8k16.row.col.f32.f16.f16.f32 "
                    "{%0,%1,%2,%3},{%4,%5,%6,%7},{%8,%9},{%0,%1,%2,%3};"
                    : "+f"(c[mt][0]), "+f"(c[mt][1]), "+f"(c[mt][2]), "+f"(c[mt][3])
                    : "r"(a[mt][ks][0]), "r"(a[mt][ks][1]), "r"(a[mt][ks][2]), "r"(a[mt][ks][3]),
                      "r"(bf[ks][0]), "r"(bf[ks][1]));
        }
        const int wdw = warp * 18 + nt * 2 + (lm4 >> 1);
        #pragma unroll
        for (int mt = 0; mt < 4; mt++) {
            s0a[mt] += c[mt][0] + c[mt][1];
            q0a[mt] += c[mt][0]*c[mt][0] + c[mt][1]*c[mt][1];
            s1a[mt] += c[mt][2] + c[mt][3];
            q1a[mt] += c[mt][2]*c[mt][2] + c[mt][3]*c[mt][3];
            float m0 = fmaxf(c[mt][0], c[mt][1]);
            float m1 = fmaxf(c[mt][2], c[mt][3]);
            m0 = fmaxf(m0, __shfl_xor_sync(0xffffffffu, m0, 1));
            m1 = fmaxf(m1, __shfl_xor_sync(0xffffffffu, m1, 1));
            if ((lm4 & 1) == 0) {
                int oc = mt * 16 + l4;
                g_pool1[b * 9216 + wdw * 64 + oc]     = m0;
                g_pool1[b * 9216 + wdw * 64 + oc + 8] = m1;
            }
        }
    }

    #pragma unroll
    for (int mt = 0; mt < 4; mt++) {
        float s0 = s0a[mt], q0 = q0a[mt], s1 = s1a[mt], q1 = q1a[mt];
        s0 += __shfl_xor_sync(0xffffffffu, s0, 1); s0 += __shfl_xor_sync(0xffffffffu, s0, 2);
        q0 += __shfl_xor_sync(0xffffffffu, q0, 1); q0 += __shfl_xor_sync(0xffffffffu, q0, 2);
        s1 += __shfl_xor_sync(0xffffffffu, s1, 1); s1 += __shfl_xor_sync(0xffffffffu, s1, 2);
        q1 += __shfl_xor_sync(0xffffffffu, q1, 1); q1 += __shfl_xor_sync(0xffffffffu, q1, 2);
        if (lm4 == 0) {
            srs[mt * 16 + l4][warp] = s0;     srq[mt * 16 + l4][warp] = q0;
            srs[mt * 16 + l4 + 8][warp] = s1; srq[mt * 16 + l4 + 8][warp] = q1;
        }
    }
    __syncthreads();
    if (t < 64) {
        float S = 0.f, Q = 0.f;
        #pragma unroll
        for (int w = 0; w < 8; w++) { S += srs[t][w]; Q += srq[t][w]; }
        g_p1sum[t * B + b] = S;
        g_p1sq [t * B + b] = Q;
    }
}

// ---------------- BN finalize: warp-per-channel, shfl-only ----------------
__global__ void k_bnfin1(const float* __restrict__ gamma, const float* __restrict__ beta) {
    const int w = threadIdx.x >> 5, lane = threadIdx.x & 31;
    const int c = blockIdx.x * 8 + w;
    const float4* ps = (const float4*)&g_p1sum[c * B];
    const float4* pq = (const float4*)&g_p1sq [c * B];
    float s = 0.f, q = 0.f;
    #pragma unroll
    for (int i = 0; i < 4; i++) {
        float4 v = ps[lane * 4 + i]; s += v.x + v.y + v.z + v.w;
        float4 u = pq[lane * 4 + i]; q += u.x + u.y + u.z + u.w;
    }
    #pragma unroll
    for (int o = 16; o; o >>= 1) {
        s += __shfl_xor_sync(0xffffffffu, s, o);
        q += __shfl_xor_sync(0xffffffffu, q, o);
    }
    if (lane == 0) {
        const float invN = 1.0f / (float)(B * 576);
        float mean = s * invN;
        float var  = q * invN - mean * mean;
        float sc = gamma[c] * rsqrtf(var + BN_EPS);
        g_scale1[c] = sc;
        g_shift1[c] = beta[c] - mean * sc;
    }
}

__global__ void k_bnfin2(const float* __restrict__ gamma, const float* __restrict__ beta) {
    const int w = threadIdx.x >> 5, lane = threadIdx.x & 31;
    const int c = blockIdx.x * 8 + w;
    const float4* ps = (const float4*)&g_p2sum[c * B];
    const float4* pq = (const float4*)&g_p2sq [c * B];
    float s = 0.f, q = 0.f;
    #pragma unroll
    for (int i = 0; i < 4; i++) {
        float4 v = ps[lane * 4 + i]; s += v.x + v.y + v.z + v.w;
        float4 u = pq[lane * 4 + i]; q += u.x + u.y + u.z + u.w;
    }
    #pragma unroll
    for (int o = 16; o; o >>= 1) {
        s += __shfl_xor_sync(0xffffffffu, s, o);
        q += __shfl_xor_sync(0xffffffffu, q, o);
    }
    if (lane == 0) {
        const float invN = 1.0f / (float)(B * 64);
        float mean = s * invN;
        float var  = q * invN - mean * mean;
        float sc = gamma[c] * rsqrtf(var + BN_EPS);
        g_scale2[c] = sc;
        g_shift2[c] = beta[c] - mean * sc;
    }
}

// ---------------- conv2: fp16 mma, 2 images/block, 256 threads, 2 blocks/SM -------------
// 8 warps: wm(2: 64 oc, mt=4) x wn(4: image=wn>>1, y-half=wn&1; 32 px, nt=4).
// Per-output k-accumulation order identical to previous rounds -> conv outputs bit-identical.
#define CV2_CSTR 72
#define CV2_IMGH (144 * CV2_CSTR)                 // 10368 halves / image
#define CV2_SX_H (2 * CV2_IMGH)                   // 20736
#define CV2_WBUF (C2 * CV2_CSTR)                  // 9216
#define CV2_SMEM_BYTES ((CV2_SX_H + 2 * CV2_WBUF) * 2)   // 78336 B -> 2 blocks/SM

__global__ __launch_bounds__(256, 2) void k_conv2() {
    extern __shared__ __half smh[];
    __half* sxh = smh;
    __half* sA0 = smh + CV2_SX_H;
    __half* sA1 = sA0 + CV2_WBUF;
    const int b2 = blockIdx.x * 2;
    const int t = threadIdx.x;
    const int lane = t & 31, warp = t >> 5;
    const int l4 = lane >> 2, lm4 = lane & 3;
    const int wm = warp >> 2, wn = warp & 3;
    const int img = wn >> 1, yh = wn & 1;         // y-half: rows yh*4 .. yh*4+3
    const int m0w = wm * 64;

    {   // stage weights for khkw=0: 128 oc x 64 ci = 1024 16B chunks, 8 chunks/oc
        const __half* wsrc = g_qw2h;
        #pragma unroll
        for (int j = 0; j < 4; j++) {
            int idx = t + 256 * j;                // 0..1023
            int oc = idx >> 3, c8 = idx & 7;
            cp16(sA0 + oc * CV2_CSTR + c8 * 8, wsrc + idx * 8);
        }
        CP_COMMIT();
    }

    // stage 2 images: BN1 + ReLU + fp16
    for (int idx = t; idx < 2 * 144 * 32; idx += 256) {
        int im = idx / 4608, r = idx - im * 4608;
        int p = r >> 5, cp = r & 31;
        int ci0 = 2 * cp;
        float2 v = *(const float2*)&g_pool1[(b2 + im) * 9216 + p * 64 + ci0];
        float v0 = fmaxf(fmaf(g_scale1[ci0],     v.x, g_shift1[ci0]),     0.0f);
        float v1 = fmaxf(fmaf(g_scale1[ci0 + 1], v.y, g_shift1[ci0 + 1]), 0.0f);
        *(__half2*)&sxh[im * CV2_IMGH + p * CV2_CSTR + ci0] = __floats2half2_rn(v0, v1);
    }

    float c[4][4][4];
    #pragma unroll
    for (int i = 0; i < 4; i++)
        #pragma unroll
        for (int j = 0; j < 4; j++)
            #pragma unroll
            for (int r = 0; r < 4; r++) c[i][j][r] = 0.f;

    for (int khkw = 0; khkw < 25; khkw++) {
        const __half* sA = (khkw & 1) ? sA1 : sA0;
        CP_WAIT0();
        __syncthreads();
        if (khkw < 24) {
            __half* dst = (khkw & 1) ? sA0 : sA1;
            const __half* wsrc = g_qw2h + (khkw + 1) * (C2 * C1);
            #pragma unroll
            for (int j = 0; j < 4; j++) {
                int idx = t + 256 * j;            // 0..1023
                int oc = idx >> 3, c8 = idx & 7;
                cp16(dst + oc * CV2_CSTR + c8 * 8, wsrc + idx * 8);
            }
            CP_COMMIT();
        }
        const int kh = khkw / 5, kw = khkw - 5 * kh;
        const __half* bbase = sxh + img * CV2_IMGH
                            + ((yh * 4 + kh) * 12 + kw + l4) * CV2_CSTR + 2 * lm4;
        #pragma unroll
        for (int ks = 0; ks < 4; ks++) {
            const int k0 = ks * 16;
            unsigned a[4][4], bf[4][2];
            #pragma unroll
            for (int mt = 0; mt < 4; mt++) {
                const __half* ap = sA + (m0w + mt * 16 + l4) * CV2_CSTR + k0 + 2 * lm4;
                a[mt][0] = *(const unsigned*)(ap);
                a[mt][1] = *(const unsigned*)(ap + 8 * CV2_CSTR);
                a[mt][2] = *(const unsigned*)(ap + 8);
                a[mt][3] = *(const unsigned*)(ap + 8 * CV2_CSTR + 8);
            }
            const __half* bp = bbase + k0;
            #pragma unroll
            for (int nt = 0; nt < 4; nt++) {
                bf[nt][0] = *(const unsigned*)(bp + nt * 12 * CV2_CSTR);
                bf[nt][1] = *(const unsigned*)(bp + nt * 12 * CV2_CSTR + 8);
            }
            #pragma unroll
            for (int mt = 0; mt < 4; mt++)
                #pragma unroll
                for (int nt = 0; nt < 4; nt++)
                    asm volatile(
                        "mma.sync.aligned.m16n8k16.row.col.f32.f16.f16.f32 "
                        "{%0,%1,%2,%3},{%4,%5,%6,%7},{%8,%9},{%0,%1,%2,%3};"
                        : "+f"(c[mt][nt][0]), "+f"(c[mt][nt][1]),
                          "+f"(c[mt][nt][2]), "+f"(c[mt][nt][3])
                        : "r"(a[mt][0]), "r"(a[mt][1]), "r"(a[mt][2]), "r"(a[mt][3]),
                          "r"(bf[nt][0]), "r"(bf[nt][1]));
        }
    }

    // epilogue: pool + BN2 partials. Protect weight-buffer reuse first.
    __syncthreads();
    float* sps = (float*)sA0;          // [h2][oc128][img2] sums
    float* spq = sps + 512;            // same for squares
    const int bimg = b2 + img;
    #pragma unroll
    for (int mt = 0; mt < 4; mt++) {
        int r0 = m0w + mt * 16 + l4;
        #pragma unroll
        for (int tp = 0; tp < 2; tp++) {
            float pA = fmaxf(fmaxf(c[mt][2*tp][0], c[mt][2*tp][1]),
                             fmaxf(c[mt][2*tp+1][0], c[mt][2*tp+1][1]));
            float pB = fmaxf(fmaxf(c[mt][2*tp][2], c[mt][2*tp][3]),
                             fmaxf(c[mt][2*tp+1][2], c[mt][2*tp+1][3]));
            int gy = yh * 2 + tp;      // global pool row
            g_h1[bimg * FLAT + r0 * 16 + gy * 4 + lm4] = pA;
            g_h1[bimg * FLAT + (r0 + 8) * 16 + gy * 4 + lm4] = pB;
        }
        float s0 = 0.f, q0 = 0.f, s1 = 0.f, q1 = 0.f;
        #pragma unroll
        for (int nt = 0; nt < 4; nt++) {
            s0 += c[mt][nt][0] + c[mt][nt][1];
            q0 += c[mt][nt][0]*c[mt][nt][0] + c[mt][nt][1]*c[mt][nt][1];
            s1 += c[mt][nt][2] + c[mt][nt][3];
            q1 += c[mt][nt][2]*c[mt][nt][2] + c[mt][nt][3]*c[mt][nt][3];
        }
        s0 += __shfl_xor_sync(0xffffffffu, s0, 1); s0 += __shfl_xor_sync(0xffffffffu, s0, 2);
        q0 += __shfl_xor_sync(0xffffffffu, q0, 1); q0 += __shfl_xor_sync(0xffffffffu, q0, 2);
        s1 += __shfl_xor_sync(0xffffffffu, s1, 1); s1 += __shfl_xor_sync(0xffffffffu, s1, 2);
        q1 += __shfl_xor_sync(0xffffffffu, q1, 1); q1 += __shfl_xor_sync(0xffffffffu, q1, 2);
        if (lm4 == 0) {
            sps[(yh * 128 + r0) * 2 + img] = s0;       spq[(yh * 128 + r0) * 2 + img] = q0;
            sps[(yh * 128 + r0 + 8) * 2 + img] = s1;   spq[(yh * 128 + r0 + 8) * 2 + img] = q1;
        }
    }
    __syncthreads();
    {   // combine the two y-halves: 256 threads = 128 oc x 2 images
        int oc = t >> 1, im = t & 1;
        float S = sps[(oc) * 2 + im] + sps[(128 + oc) * 2 + im];
        float Q = spq[(oc) * 2 + im] + spq[(128 + oc) * 2 + im];
        g_p2sum[oc * B + b2 + im] = S;
        g_p2sq [oc * B + b2 + im] = Q;
    }
}

// ---------------- fc1: fp16 mma, 32-row b-tiles (grid 16x8), BN3 partials in epilogue ---
#define FC1_STR 136
__global__ __launch_bounds__(256) void k_fc1() {
    __shared__ __half sA[32 * FC1_STR];
    __shared__ __half sB[64 * FC1_STR];
    const int t = threadIdx.x;
    const int lane = t & 31, warp = t >> 5;
    const int l4 = lane >> 2, lm4 = lane & 3;
    const int wm = warp >> 2, wn = warp & 3;
    const int b0 = blockIdx.x * 32, f0 = blockIdx.y * 64;
    const int m0w = wm * 16, n0w = wn * 16;

    float c[2][4];
    #pragma unroll
    for (int j = 0; j < 2; j++)
        #pragma unroll
        for (int r = 0; r < 4; r++) c[j][r] = 0.f;

    for (int kc = 0; kc < 16; kc++) {
        if (kc) __syncthreads();
        // A: 32 rows x 128 k halves (BN2+ReLU from fp32 g_h1)
        #pragma unroll
        for (int j = 0; j < 8; j++) {
            int idx = t + 256 * j;                 // 0..2047 half2
            int bl = idx >> 6, kp = idx & 63;
            int kg = kc * 128 + 2 * kp;
            float2 v = *(const float2*)&g_h1[(b0 + bl) * FLAT + kg];
            int c0 = kg >> 4, c1 = (kg + 1) >> 4;
            float v0 = fmaxf(fmaf(g_scale2[c0], v.x, g_shift2[c0]), 0.0f);
            float v1 = fmaxf(fmaf(g_scale2[c1], v.y, g_shift2[c1]), 0.0f);
            *(__half2*)&sA[bl * FC1_STR + 2 * kp] = __floats2half2_rn(v0, v1);
        }
        // B: 64 f x 128 k halves
        #pragma unroll
        for (int j = 0; j < 4; j++) {
            int idx = t + 256 * j;                 // 0..1023 uint4
            int fl = idx >> 4, k8 = idx & 15;
            *(uint4*)&sB[fl * FC1_STR + k8 * 8] =
                *(const uint4*)&g_qf1h[(f0 + fl) * FLAT + kc * 128 + k8 * 8];
        }
        __syncthreads();
        #pragma unroll
        for (int ks = 0; ks < 8; ks++) {
            const int k0 = ks * 16;
            unsigned a[4], bf[2][2];
            {
                const __half* ap = sA + (m0w + l4) * FC1_STR + k0 + 2 * lm4;
                a[0] = *(const unsigned*)(ap);
                a[1] = *(const unsigned*)(ap + 8 * FC1_STR);
                a[2] = *(const unsigned*)(ap + 8);
                a[3] = *(const unsigned*)(ap + 8 * FC1_STR + 8);
            }
            #pragma unroll
            for (int nt = 0; nt < 2; nt++) {
                const __half* bp = sB + (n0w + nt * 8 + l4) * FC1_STR + k0 + 2 * lm4;
                bf[nt][0] = *(const unsigned*)(bp);
                bf[nt][1] = *(const unsigned*)(bp + 8);
            }
            #pragma unroll
            for (int nt = 0; nt < 2; nt++)
                asm volatile(
                    "mma.sync.aligned.m16n8k16.row.col.f32.f16.f16.f32 "
                    "{%0,%1,%2,%3},{%4,%5,%6,%7},{%8,%9},{%0,%1,%2,%3};"
                    : "+f"(c[nt][0]), "+f"(c[nt][1]), "+f"(c[nt][2]), "+f"(c[nt][3])
                    : "r"(a[0]), "r"(a[1]), "r"(a[2]), "r"(a[3]),
                      "r"(bf[nt][0]), "r"(bf[nt][1]));
        }
    }
    {
        int rA = b0 + m0w + l4;
        #pragma unroll
        for (int nt = 0; nt < 2; nt++) {
            int cc = f0 + n0w + nt * 8 + 2 * lm4;
            *(float2*)&g_fc1[rA * F1 + cc]       = make_float2(c[nt][0], c[nt][1]);
            *(float2*)&g_fc1[(rA + 8) * F1 + cc] = make_float2(c[nt][2], c[nt][3]);
        }
    }
    // BN3 partials: per-feature sum/sumsq over this block's 32 batch rows
    __syncthreads();
    float* srs = (float*)sB;            // [2 wm][64 f]
    float* srq = srs + 128;
    #pragma unroll
    for (int nt = 0; nt < 2; nt++) {
        #pragma unroll
        for (int j = 0; j < 2; j++) {
            float s = c[nt][j] + c[nt][j + 2];
            float q = c[nt][j]*c[nt][j] + c[nt][j+2]*c[nt][j+2];
            #pragma unroll
            for (int o = 4; o < 32; o <<= 1) {
                s += __shfl_xor_sync(0xffffffffu, s, o);
                q += __shfl_xor_sync(0xffffffffu, q, o);
            }
            if (l4 == 0) {
                int fl = n0w + nt * 8 + 2 * lm4 + j;
                srs[wm * 64 + fl] = s;
                srq[wm * 64 + fl] = q;
            }
        }
    }
    __syncthreads();
    if (t < 64) {
        float S = srs[t] + srs[64 + t];
        float Q = srq[t] + srq[64 + t];
        g_p3s[(f0 + t) * 16 + blockIdx.x] = S;
        g_p3q[(f0 + t) * 16 + blockIdx.x] = Q;
    }
}

// ---------------- fc2: BN3 finalize (redundant per block) + bn3+relu+fc2 ----------------
__global__ __launch_bounds__(256) void k_fc2(const float* __restrict__ fc2_b,
                                             const float* __restrict__ bn3_g,
                                             const float* __restrict__ bn3_b,
                                             float* __restrict__ out) {
    __shared__ float swq[F2 * F1];
    __shared__ float sscale[F1], sshift[F1];
    __shared__ float sbias[F2];
    const int t = threadIdx.x;
    for (int i = t; i < F2 * F1; i += 256) swq[i] = g_qf2[i];
    if (t < F2) sbias[t] = fc2_b[t];
    #pragma unroll
    for (int j = 0; j < 2; j++) {
        int f = t + 256 * j;
        float S = 0.f, Q = 0.f;
        #pragma unroll
        for (int u = 0; u < 4; u++) {
            float4 sv = *(const float4*)&g_p3s[f * 16 + 4 * u];
            float4 qv = *(const float4*)&g_p3q[f * 16 + 4 * u];
            S += sv.x + sv.y + sv.z + sv.w;
            Q += qv.x + qv.y + qv.z + qv.w;
        }
        const float invN = 1.0f / (float)B;
        float mean = S * invN;
        float var  = Q * invN - mean * mean;
        float sc = bn3_g[f] * rsqrtf(var + BN_EPS);
        sscale[f] = sc;
        sshift[f] = bn3_b[f] - mean * sc;
    }
    __syncthreads();
    const int warp = t >> 5, lane = t & 31;
    const int b = blockIdx.x * 8 + warp;
    float h[16];
    #pragma unroll
    for (int i = 0; i < 16; i++) {
        int f = lane + 32 * i;
        float v = g_fc1[b * F1 + f];
        h[i] = fmaxf(fmaf(sscale[f], v, sshift[f]), 0.0f);
    }
    #pragma unroll
    for (int o = 0; o < F2; o++) {
        float acc = 0.f;
        #pragma unroll
        for (int i = 0; i < 16; i++)
            acc = fmaf(h[i], swq[o * F1 + lane + 32 * i], acc);
        #pragma unroll
        for (int s = 16; s; s >>= 1)
            acc += __shfl_xor_sync(0xffffffffu, acc, s);
        if (lane == 0) out[b * F2 + o] = acc + sbias[o];
    }
}

// ---------------- launcher ----------------
extern "C" void kernel_launch(void* const* d_in, const int* in_sizes, int n_in,
                              void* d_out, int out_size) {
    const float* x       = (const float*)d_in[0];
    const float* conv1_w = (const float*)d_in[1];
    const float* bn1_g   = (const float*)d_in[3];
    const float* bn1_b   = (const float*)d_in[4];
    const float* conv2_w = (const float*)d_in[5];
    const float* bn2_g   = (const float*)d_in[7];
    const float* bn2_b   = (const float*)d_in[8];
    const float* fc1_w   = (const float*)d_in[9];
    const float* bn3_g   = (const float*)d_in[11];
    const float* bn3_b   = (const float*)d_in[12];
    const float* fc2_w   = (const float*)d_in[13];
    const float* fc2_b   = (const float*)d_in[14];
    float* out = (float*)d_out;

    cudaFuncSetAttribute(k_conv1, cudaFuncAttributeMaxDynamicSharedMemorySize, CV1_SMEM_BYTES);
    cudaFuncSetAttribute(k_conv2, cudaFuncAttributeMaxDynamicSharedMemorySize, CV2_SMEM_BYTES);

    // quantization (conv/fc biases dropped: train-mode BN cancels them exactly)
    k_absmax_all<<<dim3(128, 4), 256>>>(conv1_w, conv2_w, fc1_w, fc2_w);
    k_quant_all <<<dim3(128, 4), 256>>>(conv1_w, conv2_w, fc1_w, fc2_w);

    // stage 1
    k_conv1<<<B, 256, CV1_SMEM_BYTES>>>(x);
    k_bnfin1<<<8, 256>>>(bn1_g, bn1_b);

    // stage 2 (2 images/block, 256 blocks, 2 blocks/SM)
    k_conv2<<<B / 2, 256, CV2_SMEM_BYTES>>>();
    k_bnfin2<<<16, 256>>>(bn2_g, bn2_b);

    // stage 3 (32-row b-tiles: 128 blocks; BN3 stats finalized inside fc2)
    k_fc1<<<dim3(16, 8), 256>>>();
    k_fc2<<<B / 8, 256>>>(fc2_b, bn3_g, bn3_b, out);
}

// round 11
// speedup vs baseline: 1.3631x; 1.0427x over previous
#include <cuda_runtime.h>
#include <cuda_fp16.h>
#include <cuda_bf16.h>

// ---------------- problem constants ----------------
#define B      512
#define C1     64
#define C2     128
#define FLAT   2048
#define F1     512
#define F2     10
#define BN_EPS 1e-5f

// ---------------- device scratch ----------------
__device__ unsigned g_maxabs[4];                  // zero-init; atomicMax idempotent across replays
__device__ __half g_qw2h[25 * C2 * C1];           // conv2 ternary [khkw][oc][ci]
__device__ __half g_qf1h[F1 * FLAT];              // fc1 ternary [f][k]
__device__ float  g_qf2[F2 * F1];
__device__ float g_pool1[B * 144 * C1];           // RAW pooled conv1 (pre-BN), [b][pixel][ci]
__device__ float g_p1sum[C1 * B], g_p1sq[C1 * B];
__device__ float g_scale1[C1], g_shift1[C1];
__device__ float g_p2sum[C2 * B], g_p2sq[C2 * B];
__device__ float g_scale2[C2], g_shift2[C2];
__device__ float g_h1[B * FLAT];                  // RAW pooled conv2 (pre-BN)
__device__ float g_fc1[B * F1];                   // RAW fc1 (pre-BN)
__device__ float g_p3s[F1 * 16], g_p3q[F1 * 16];  // BN3 partials: [feature][b-tile]

// ---------------- cp.async helpers ----------------
__device__ __forceinline__ void cp16(__half* smem_dst, const __half* gsrc) {
    unsigned s = (unsigned)__cvta_generic_to_shared(smem_dst);
    asm volatile("cp.async.cg.shared.global [%0], [%1], 16;\n" :: "r"(s), "l"(gsrc));
}
#define CP_COMMIT() asm volatile("cp.async.commit_group;\n" ::: "memory")
#define CP_WAIT0()  asm volatile("cp.async.wait_group 0;\n" ::: "memory")

// ---------------- quantization ----------------
__global__ void k_absmax_all(const float* __restrict__ w0, const float* __restrict__ w1,
                             const float* __restrict__ w2, const float* __restrict__ w3) {
    cudaTriggerProgrammaticLaunchCompletion();
    const int slot = blockIdx.y;
    const float* w = (slot == 0) ? w0 : (slot == 1) ? w1 : (slot == 2) ? w2 : w3;
    const int n4 = ((slot == 0) ? 1600 : (slot == 1) ? 204800 : (slot == 2) ? 1048576 : 5120) >> 2;
    const float4* w4 = (const float4*)w;
    unsigned m = 0u;
    #pragma unroll 4
    for (int i = blockIdx.x * blockDim.x + threadIdx.x; i < n4; i += gridDim.x * blockDim.x) {
        float4 v = w4[i];
        m = max(m, __float_as_uint(fabsf(v.x)));
        m = max(m, __float_as_uint(fabsf(v.y)));
        m = max(m, __float_as_uint(fabsf(v.z)));
        m = max(m, __float_as_uint(fabsf(v.w)));
    }
    #pragma unroll
    for (int o = 16; o; o >>= 1)
        m = max(m, __shfl_xor_sync(0xffffffffu, m, o));
    if ((threadIdx.x & 31) == 0) atomicMax(&g_maxabs[slot], m);
}

// slots 1..3 only (conv1 weights quantized inline in k_conv1)
__global__ void k_quant_all(const float* __restrict__ w1,
                            const float* __restrict__ w2, const float* __restrict__ w3) {
    cudaTriggerProgrammaticLaunchCompletion();   // conv1 doesn't consume us; let it launch
    cudaGridDependencySynchronize();             // need g_maxabs from absmax
    const int slot = blockIdx.y + 1;
    const float* w = (slot == 1) ? w1 : (slot == 2) ? w2 : w3;
    const int n4 = ((slot == 1) ? 204800 : (slot == 2) ? 1048576 : 5120) >> 2;
    const float4* w4 = (const float4*)w;
    const float t = 0.05f * __uint_as_float(g_maxabs[slot]);
    #pragma unroll 2
    for (int i = blockIdx.x * blockDim.x + threadIdx.x; i < n4; i += gridDim.x * blockDim.x) {
        float4 v = w4[i];
        float q0 = (v.x > t) ? 1.0f : ((v.x < -t) ? -1.0f : 0.0f);
        float q1 = (v.y > t) ? 1.0f : ((v.y < -t) ? -1.0f : 0.0f);
        float q2 = (v.z > t) ? 1.0f : ((v.z < -t) ? -1.0f : 0.0f);
        float q3 = (v.w > t) ? 1.0f : ((v.w < -t) ? -1.0f : 0.0f);
        int base = 4 * i;
        if (slot == 1) {
            float qs[4] = {q0, q1, q2, q3};
            #pragma unroll
            for (int u = 0; u < 4; u++) {
                int idx = base + u;
                int oc = idx / 1600, rem = idx - oc * 1600, ci = rem / 25, kk = rem - ci * 25;
                g_qw2h[kk * (C2 * C1) + oc * C1 + ci] = __float2half(qs[u]);
            }
        } else if (slot == 2) {
            *(__half2*)&g_qf1h[base]     = __floats2half2_rn(q0, q1);
            *(__half2*)&g_qf1h[base + 2] = __floats2half2_rn(q2, q3);
        } else {
            *(float4*)&g_qf2[base] = make_float4(q0, q1, q2, q3);
        }
    }
}

// ---------------- conv1: fp16 mma, pool-window-major N; weights quantized inline --------
// Depends only on absmax (2 launches back) -> NO gridDepSync: runs concurrent with quant.
#define CV1_SMEM_BYTES (3136 + 5120 + 46080)
__global__ __launch_bounds__(256) void k_conv1(const float* __restrict__ x,
                                               const float* __restrict__ w1raw) {
    cudaTriggerProgrammaticLaunchCompletion();
    extern __shared__ char c1sm[];
    float*  sxf = (float*)c1sm;
    __half* sA  = (__half*)(c1sm + 3136);
    __half* sB  = (__half*)(c1sm + 3136 + 5120);
    __shared__ float srs[64][9], srq[64][9];
    const int b = blockIdx.x, t = threadIdx.x;
    const int lane = t & 31, warp = t >> 5;
    const int l4 = lane >> 2, lm4 = lane & 3;

    for (int i = t; i < 784; i += 256) sxf[i] = x[b * 784 + i];
    // inline ternary quantization of conv1 weights (same values as before -> bit-identical)
    {
        const float tq = 0.05f * __uint_as_float(g_maxabs[0]);
        for (int i = t; i < 1600; i += 256) {
            int oc = i / 25, k = i - oc * 25;
            float v = w1raw[i];
            sA[oc * 40 + k] = __float2half((v > tq) ? 1.0f : ((v < -tq) ? -1.0f : 0.0f));
        }
        for (int i = t; i < 64 * 7; i += 256) {   // zero pad k=25..31 (fragments read k<32)
            int oc = i / 7, k = 25 + i % 7;
            sA[oc * 40 + k] = __ushort_as_half((unsigned short)0);
        }
    }
    __syncthreads();

    {
        const int kp = t & 15, n0 = t >> 4;
        const int k0 = 2 * kp;
        const int kh0 = k0 / 5, kw0 = k0 - 5 * kh0;
        const int kh1 = (k0 + 1) / 5, kw1 = (k0 + 1) - 5 * kh1;
        const bool e0 = (k0 < 25), e1 = (k0 + 1 < 25);
        #pragma unroll 4
        for (int st = 0; st < 36; st++) {
            int n = n0 + 16 * st;
            int w = n >> 2, j = n & 3;
            int py = w / 12, px = w - 12 * py;
            int iy = 2 * py + (j >> 1), ix = 2 * px + (j & 1);
            float v0 = e0 ? sxf[(iy + kh0) * 28 + ix + kw0] : 0.f;
            float v1 = e1 ? sxf[(iy + kh1) * 28 + ix + kw1] : 0.f;
            *(__half2*)&sB[n * 40 + k0] = __floats2half2_rn(v0, v1);
        }
    }
    __syncthreads();

    unsigned a[4][2][4];
    #pragma unroll
    for (int mt = 0; mt < 4; mt++) {
        const __half* ap = sA + (mt * 16 + l4) * 40 + 2 * lm4;
        #pragma unroll
        for (int ks = 0; ks < 2; ks++) {
            a[mt][ks][0] = *(const unsigned*)(ap + 16 * ks);
            a[mt][ks][1] = *(const unsigned*)(ap + 16 * ks + 8 * 40);
            a[mt][ks][2] = *(const unsigned*)(ap + 16 * ks + 8);
            a[mt][ks][3] = *(const unsigned*)(ap + 16 * ks + 8 * 40 + 8);
        }
    }

    float s0a[4] = {0,0,0,0}, s1a[4] = {0,0,0,0};
    float q0a[4] = {0,0,0,0}, q1a[4] = {0,0,0,0};

    #pragma unroll
    for (int nt = 0; nt < 9; nt++) {
        const __half* bp = sB + (warp * 72 + nt * 8 + l4) * 40 + 2 * lm4;
        unsigned bf[2][2];
        #pragma unroll
        for (int ks = 0; ks < 2; ks++) {
            bf[ks][0] = *(const unsigned*)(bp + 16 * ks);
            bf[ks][1] = *(const unsigned*)(bp + 16 * ks + 8);
        }
        float c[4][4];
        #pragma unroll
        for (int mt = 0; mt < 4; mt++) {
            c[mt][0] = c[mt][1] = c[mt][2] = c[mt][3] = 0.f;
            #pragma unroll
            for (int ks = 0; ks < 2; ks++)
                asm volatile(
                    "mma.sync.aligned.m16n8k16.row.col.f32.f16.f16.f32 "
                    "{%0,%1,%2,%3},{%4,%5,%6,%7},{%8,%9},{%0,%1,%2,%3};"
                    : "+f"(c[mt][0]), "+f"(c[mt][1]), "+f"(c[mt][2]), "+f"(c[mt][3])
                    : "r"(a[mt][ks][0]), "r"(a[mt][ks][1]), "r"(a[mt][ks][2]), "r"(a[mt][ks][3]),
                      "r"(bf[ks][0]), "r"(bf[ks][1]));
        }
        const int wdw = warp * 18 + nt * 2 + (lm4 >> 1);
        #pragma unroll
        for (int mt = 0; mt < 4; mt++) {
            s0a[mt] += c[mt][0] + c[mt][1];
            q0a[mt] += c[mt][0]*c[mt][0] + c[mt][1]*c[mt][1];
            s1a[mt] += c[mt][2] + c[mt][3];
            q1a[mt] += c[mt][2]*c[mt][2] + c[mt][3]*c[mt][3];
            float m0 = fmaxf(c[mt][0], c[mt][1]);
            float m1 = fmaxf(c[mt][2], c[mt][3]);
            m0 = fmaxf(m0, __shfl_xor_sync(0xffffffffu, m0, 1));
            m1 = fmaxf(m1, __shfl_xor_sync(0xffffffffu, m1, 1));
            if ((lm4 & 1) == 0) {
                int oc = mt * 16 + l4;
                g_pool1[b * 9216 + wdw * 64 + oc]     = m0;
                g_pool1[b * 9216 + wdw * 64 + oc + 8] = m1;
            }
        }
    }

    #pragma unroll
    for (int mt = 0; mt < 4; mt++) {
        float s0 = s0a[mt], q0 = q0a[mt], s1 = s1a[mt], q1 = q1a[mt];
        s0 += __shfl_xor_sync(0xffffffffu, s0, 1); s0 += __shfl_xor_sync(0xffffffffu, s0, 2);
        q0 += __shfl_xor_sync(0xffffffffu, q0, 1); q0 += __shfl_xor_sync(0xffffffffu, q0, 2);
        s1 += __shfl_xor_sync(0xffffffffu, s1, 1); s1 += __shfl_xor_sync(0xffffffffu, s1, 2);
        q1 += __shfl_xor_sync(0xffffffffu, q1, 1); q1 += __shfl_xor_sync(0xffffffffu, q1, 2);
        if (lm4 == 0) {
            srs[mt * 16 + l4][warp] = s0;     srq[mt * 16 + l4][warp] = q0;
            srs[mt * 16 + l4 + 8][warp] = s1; srq[mt * 16 + l4 + 8][warp] = q1;
        }
    }
    __syncthreads();
    if (t < 64) {
        float S = 0.f, Q = 0.f;
        #pragma unroll
        for (int w = 0; w < 8; w++) { S += srs[t][w]; Q += srq[t][w]; }
        g_p1sum[t * B + b] = S;
        g_p1sq [t * B + b] = Q;
    }
}

// ---------------- BN finalize: warp-per-channel, shfl-only ----------------
__global__ void k_bnfin1(const float* __restrict__ gamma, const float* __restrict__ beta) {
    cudaTriggerProgrammaticLaunchCompletion();   // lets conv2 pre-stage weights
    cudaGridDependencySynchronize();             // need conv1 partials
    const int w = threadIdx.x >> 5, lane = threadIdx.x & 31;
    const int c = blockIdx.x * 8 + w;
    const float4* ps = (const float4*)&g_p1sum[c * B];
    const float4* pq = (const float4*)&g_p1sq [c * B];
    float s = 0.f, q = 0.f;
    #pragma unroll
    for (int i = 0; i < 4; i++) {
        float4 v = ps[lane * 4 + i]; s += v.x + v.y + v.z + v.w;
        float4 u = pq[lane * 4 + i]; q += u.x + u.y + u.z + u.w;
    }
    #pragma unroll
    for (int o = 16; o; o >>= 1) {
        s += __shfl_xor_sync(0xffffffffu, s, o);
        q += __shfl_xor_sync(0xffffffffu, q, o);
    }
    if (lane == 0) {
        const float invN = 1.0f / (float)(B * 576);
        float mean = s * invN;
        float var  = q * invN - mean * mean;
        float sc = gamma[c] * rsqrtf(var + BN_EPS);
        g_scale1[c] = sc;
        g_shift1[c] = beta[c] - mean * sc;
    }
}

__global__ void k_bnfin2(const float* __restrict__ gamma, const float* __restrict__ beta) {
    cudaTriggerProgrammaticLaunchCompletion();   // lets fc1 pre-stage weights
    cudaGridDependencySynchronize();             // need conv2 partials
    const int w = threadIdx.x >> 5, lane = threadIdx.x & 31;
    const int c = blockIdx.x * 8 + w;
    const float4* ps = (const float4*)&g_p2sum[c * B];
    const float4* pq = (const float4*)&g_p2sq [c * B];
    float s = 0.f, q = 0.f;
    #pragma unroll
    for (int i = 0; i < 4; i++) {
        float4 v = ps[lane * 4 + i]; s += v.x + v.y + v.z + v.w;
        float4 u = pq[lane * 4 + i]; q += u.x + u.y + u.z + u.w;
    }
    #pragma unroll
    for (int o = 16; o; o >>= 1) {
        s += __shfl_xor_sync(0xffffffffu, s, o);
        q += __shfl_xor_sync(0xffffffffu, q, o);
    }
    if (lane == 0) {
        const float invN = 1.0f / (float)(B * 64);
        float mean = s * invN;
        float var  = q * invN - mean * mean;
        float sc = gamma[c] * rsqrtf(var + BN_EPS);
        g_scale2[c] = sc;
        g_shift2[c] = beta[c] - mean * sc;
    }
}

// ---------------- conv2: fp16 mma, 2 images/block, 256 threads, 2 blocks/SM -------------
#define CV2_CSTR 72
#define CV2_IMGH (144 * CV2_CSTR)
#define CV2_SX_H (2 * CV2_IMGH)
#define CV2_WBUF (C2 * CV2_CSTR)
#define CV2_SMEM_BYTES ((CV2_SX_H + 2 * CV2_WBUF) * 2)

__global__ __launch_bounds__(256, 2) void k_conv2() {
    cudaTriggerProgrammaticLaunchCompletion();
    extern __shared__ __half smh[];
    __half* sxh = smh;
    __half* sA0 = smh + CV2_SX_H;
    __half* sA1 = sA0 + CV2_WBUF;
    const int b2 = blockIdx.x * 2;
    const int t = threadIdx.x;
    const int lane = t & 31, warp = t >> 5;
    const int l4 = lane >> 2, lm4 = lane & 3;
    const int wm = warp >> 2, wn = warp & 3;
    const int img = wn >> 1, yh = wn & 1;
    const int m0w = wm * 64;

    {   // weights from quant (2 launches back: complete) — overlap with bnfin1
        const __half* wsrc = g_qw2h;
        #pragma unroll
        for (int j = 0; j < 4; j++) {
            int idx = t + 256 * j;
            int oc = idx >> 3, c8 = idx & 7;
            cp16(sA0 + oc * CV2_CSTR + c8 * 8, wsrc + idx * 8);
        }
        CP_COMMIT();
    }

    cudaGridDependencySynchronize();             // need scale1/shift1 from bnfin1

    for (int idx = t; idx < 2 * 144 * 32; idx += 256) {
        int im = idx / 4608, r = idx - im * 4608;
        int p = r >> 5, cp = r & 31;
        int ci0 = 2 * cp;
        float2 v = *(const float2*)&g_pool1[(b2 + im) * 9216 + p * 64 + ci0];
        float v0 = fmaxf(fmaf(g_scale1[ci0],     v.x, g_shift1[ci0]),     0.0f);
        float v1 = fmaxf(fmaf(g_scale1[ci0 + 1], v.y, g_shift1[ci0 + 1]), 0.0f);
        *(__half2*)&sxh[im * CV2_IMGH + p * CV2_CSTR + ci0] = __floats2half2_rn(v0, v1);
    }

    float c[4][4][4];
    #pragma unroll
    for (int i = 0; i < 4; i++)
        #pragma unroll
        for (int j = 0; j < 4; j++)
            #pragma unroll
            for (int r = 0; r < 4; r++) c[i][j][r] = 0.f;

    for (int khkw = 0; khkw < 25; khkw++) {
        const __half* sA = (khkw & 1) ? sA1 : sA0;
        CP_WAIT0();
        __syncthreads();
        if (khkw < 24) {
            __half* dst = (khkw & 1) ? sA0 : sA1;
            const __half* wsrc = g_qw2h + (khkw + 1) * (C2 * C1);
            #pragma unroll
            for (int j = 0; j < 4; j++) {
                int idx = t + 256 * j;
                int oc = idx >> 3, c8 = idx & 7;
                cp16(dst + oc * CV2_CSTR + c8 * 8, wsrc + idx * 8);
            }
            CP_COMMIT();
        }
        const int kh = khkw / 5, kw = khkw - 5 * kh;
        const __half* bbase = sxh + img * CV2_IMGH
                            + ((yh * 4 + kh) * 12 + kw + l4) * CV2_CSTR + 2 * lm4;
        #pragma unroll
        for (int ks = 0; ks < 4; ks++) {
            const int k0 = ks * 16;
            unsigned a[4][4], bf[4][2];
            #pragma unroll
            for (int mt = 0; mt < 4; mt++) {
                const __half* ap = sA + (m0w + mt * 16 + l4) * CV2_CSTR + k0 + 2 * lm4;
                a[mt][0] = *(const unsigned*)(ap);
                a[mt][1] = *(const unsigned*)(ap + 8 * CV2_CSTR);
                a[mt][2] = *(const unsigned*)(ap + 8);
                a[mt][3] = *(const unsigned*)(ap + 8 * CV2_CSTR + 8);
            }
            const __half* bp = bbase + k0;
            #pragma unroll
            for (int nt = 0; nt < 4; nt++) {
                bf[nt][0] = *(const unsigned*)(bp + nt * 12 * CV2_CSTR);
                bf[nt][1] = *(const unsigned*)(bp + nt * 12 * CV2_CSTR + 8);
            }
            #pragma unroll
            for (int mt = 0; mt < 4; mt++)
                #pragma unroll
                for (int nt = 0; nt < 4; nt++)
                    asm volatile(
                        "mma.sync.aligned.m16n8k16.row.col.f32.f16.f16.f32 "
                        "{%0,%1,%2,%3},{%4,%5,%6,%7},{%8,%9},{%0,%1,%2,%3};"
                        : "+f"(c[mt][nt][0]), "+f"(c[mt][nt][1]),
                          "+f"(c[mt][nt][2]), "+f"(c[mt][nt][3])
                        : "r"(a[mt][0]), "r"(a[mt][1]), "r"(a[mt][2]), "r"(a[mt][3]),
                          "r"(bf[nt][0]), "r"(bf[nt][1]));
        }
    }

    __syncthreads();
    float* sps = (float*)sA0;
    float* spq = sps + 512;
    const int bimg = b2 + img;
    #pragma unroll
    for (int mt = 0; mt < 4; mt++) {
        int r0 = m0w + mt * 16 + l4;
        #pragma unroll
        for (int tp = 0; tp < 2; tp++) {
            float pA = fmaxf(fmaxf(c[mt][2*tp][0], c[mt][2*tp][1]),
                             fmaxf(c[mt][2*tp+1][0], c[mt][2*tp+1][1]));
            float pB = fmaxf(fmaxf(c[mt][2*tp][2], c[mt][2*tp][3]),
                             fmaxf(c[mt][2*tp+1][2], c[mt][2*tp+1][3]));
            int gy = yh * 2 + tp;
            g_h1[bimg * FLAT + r0 * 16 + gy * 4 + lm4] = pA;
            g_h1[bimg * FLAT + (r0 + 8) * 16 + gy * 4 + lm4] = pB;
        }
        float s0 = 0.f, q0 = 0.f, s1 = 0.f, q1 = 0.f;
        #pragma unroll
        for (int nt = 0; nt < 4; nt++) {
            s0 += c[mt][nt][0] + c[mt][nt][1];
            q0 += c[mt][nt][0]*c[mt][nt][0] + c[mt][nt][1]*c[mt][nt][1];
            s1 += c[mt][nt][2] + c[mt][nt][3];
            q1 += c[mt][nt][2]*c[mt][nt][2] + c[mt][nt][3]*c[mt][nt][3];
        }
        s0 += __shfl_xor_sync(0xffffffffu, s0, 1); s0 += __shfl_xor_sync(0xffffffffu, s0, 2);
        q0 += __shfl_xor_sync(0xffffffffu, q0, 1); q0 += __shfl_xor_sync(0xffffffffu, q0, 2);
        s1 += __shfl_xor_sync(0xffffffffu, s1, 1); s1 += __shfl_xor_sync(0xffffffffu, s1, 2);
        q1 += __shfl_xor_sync(0xffffffffu, q1, 1); q1 += __shfl_xor_sync(0xffffffffu, q1, 2);
        if (lm4 == 0) {
            sps[(yh * 128 + r0) * 2 + img] = s0;       spq[(yh * 128 + r0) * 2 + img] = q0;
            sps[(yh * 128 + r0 + 8) * 2 + img] = s1;   spq[(yh * 128 + r0 + 8) * 2 + img] = q1;
        }
    }
    __syncthreads();
    {
        int oc = t >> 1, im = t & 1;
        float S = sps[(oc) * 2 + im] + sps[(128 + oc) * 2 + im];
        float Q = spq[(oc) * 2 + im] + spq[(128 + oc) * 2 + im];
        g_p2sum[oc * B + b2 + im] = S;
        g_p2sq [oc * B + b2 + im] = Q;
    }
}

// ---------------- fc1: fp16 mma, 32-row b-tiles (grid 16x8), BN3 partials in epilogue ---
#define FC1_STR 136
__global__ __launch_bounds__(256) void k_fc1() {
    cudaTriggerProgrammaticLaunchCompletion();
    __shared__ __half sA[32 * FC1_STR];
    __shared__ __half sB[64 * FC1_STR];
    const int t = threadIdx.x;
    const int lane = t & 31, warp = t >> 5;
    const int l4 = lane >> 2, lm4 = lane & 3;
    const int wm = warp >> 2, wn = warp & 3;
    const int b0 = blockIdx.x * 32, f0 = blockIdx.y * 64;
    const int m0w = wm * 16, n0w = wn * 16;

    float c[2][4];
    #pragma unroll
    for (int j = 0; j < 2; j++)
        #pragma unroll
        for (int r = 0; r < 4; r++) c[j][r] = 0.f;

    for (int kc = 0; kc < 16; kc++) {
        if (kc) __syncthreads();
        // B first (weights from quant — long complete); overlaps bnfin2 on kc==0
        #pragma unroll
        for (int j = 0; j < 4; j++) {
            int idx = t + 256 * j;
            int fl = idx >> 4, k8 = idx & 15;
            *(uint4*)&sB[fl * FC1_STR + k8 * 8] =
                *(const uint4*)&g_qf1h[(f0 + fl) * FLAT + kc * 128 + k8 * 8];
        }
        if (kc == 0) cudaGridDependencySynchronize();   // need scale2/shift2 from bnfin2
        // A: 32 rows x 128 k halves (BN2+ReLU from fp32 g_h1)
        #pragma unroll
        for (int j = 0; j < 8; j++) {
            int idx = t + 256 * j;
            int bl = idx >> 6, kp = idx & 63;
            int kg = kc * 128 + 2 * kp;
            float2 v = *(const float2*)&g_h1[(b0 + bl) * FLAT + kg];
            int c0 = kg >> 4, c1 = (kg + 1) >> 4;
            float v0 = fmaxf(fmaf(g_scale2[c0], v.x, g_shift2[c0]), 0.0f);
            float v1 = fmaxf(fmaf(g_scale2[c1], v.y, g_shift2[c1]), 0.0f);
            *(__half2*)&sA[bl * FC1_STR + 2 * kp] = __floats2half2_rn(v0, v1);
        }
        __syncthreads();
        #pragma unroll
        for (int ks = 0; ks < 8; ks++) {
            const int k0 = ks * 16;
            unsigned a[4], bf[2][2];
            {
                const __half* ap = sA + (m0w + l4) * FC1_STR + k0 + 2 * lm4;
                a[0] = *(const unsigned*)(ap);
                a[1] = *(const unsigned*)(ap + 8 * FC1_STR);
                a[2] = *(const unsigned*)(ap + 8);
                a[3] = *(const unsigned*)(ap + 8 * FC1_STR + 8);
            }
            #pragma unroll
            for (int nt = 0; nt < 2; nt++) {
                const __half* bp = sB + (n0w + nt * 8 + l4) * FC1_STR + k0 + 2 * lm4;
                bf[nt][0] = *(const unsigned*)(bp);
                bf[nt][1] = *(const unsigned*)(bp + 8);
            }
            #pragma unroll
            for (int nt = 0; nt < 2; nt++)
                asm volatile(
                    "mma.sync.aligned.m16n8k16.row.col.f32.f16.f16.f32 "
                    "{%0,%1,%2,%3},{%4,%5,%6,%7},{%8,%9},{%0,%1,%2,%3};"
                    : "+f"(c[nt][0]), "+f"(c[nt][1]), "+f"(c[nt][2]), "+f"(c[nt][3])
                    : "r"(a[0]), "r"(a[1]), "r"(a[2]), "r"(a[3]),
                      "r"(bf[nt][0]), "r"(bf[nt][1]));
        }
    }
    {
        int rA = b0 + m0w + l4;
        #pragma unroll
        for (int nt = 0; nt < 2; nt++) {
            int cc = f0 + n0w + nt * 8 + 2 * lm4;
            *(float2*)&g_fc1[rA * F1 + cc]       = make_float2(c[nt][0], c[nt][1]);
            *(float2*)&g_fc1[(rA + 8) * F1 + cc] = make_float2(c[nt][2], c[nt][3]);
        }
    }
    __syncthreads();
    float* srs = (float*)sB;
    float* srq = srs + 128;
    #pragma unroll
    for (int nt = 0; nt < 2; nt++) {
        #pragma unroll
        for (int j = 0; j < 2; j++) {
            float s = c[nt][j] + c[nt][j + 2];
            float q = c[nt][j]*c[nt][j] + c[nt][j+2]*c[nt][j+2];
            #pragma unroll
            for (int o = 4; o < 32; o <<= 1) {
                s += __shfl_xor_sync(0xffffffffu, s, o);
                q += __shfl_xor_sync(0xffffffffu, q, o);
            }
            if (l4 == 0) {
                int fl = n0w + nt * 8 + 2 * lm4 + j;
                srs[wm * 64 + fl] = s;
                srq[wm * 64 + fl] = q;
            }
        }
    }
    __syncthreads();
    if (t < 64) {
        float S = srs[t] + srs[64 + t];
        float Q = srq[t] + srq[64 + t];
        g_p3s[(f0 + t) * 16 + blockIdx.x] = S;
        g_p3q[(f0 + t) * 16 + blockIdx.x] = Q;
    }
}

// ---------------- fc2: BN3 finalize (redundant per block) + bn3+relu+fc2 ----------------
__global__ __launch_bounds__(256) void k_fc2(const float* __restrict__ fc2_b,
                                             const float* __restrict__ bn3_g,
                                             const float* __restrict__ bn3_b,
                                             float* __restrict__ out) {
    cudaTriggerProgrammaticLaunchCompletion();
    __shared__ float swq[F2 * F1];
    __shared__ float sscale[F1], sshift[F1];
    __shared__ float sbias[F2];
    const int t = threadIdx.x;
    for (int i = t; i < F2 * F1; i += 256) swq[i] = g_qf2[i];   // old data: overlap fc1
    if (t < F2) sbias[t] = fc2_b[t];
    cudaGridDependencySynchronize();             // need g_p3s/g_p3q/g_fc1 from fc1
    #pragma unroll
    for (int j = 0; j < 2; j++) {
        int f = t + 256 * j;
        float S = 0.f, Q = 0.f;
        #pragma unroll
        for (int u = 0; u < 4; u++) {
            float4 sv = *(const float4*)&g_p3s[f * 16 + 4 * u];
            float4 qv = *(const float4*)&g_p3q[f * 16 + 4 * u];
            S += sv.x + sv.y + sv.z + sv.w;
            Q += qv.x + qv.y + qv.z + qv.w;
        }
        const float invN = 1.0f / (float)B;
        float mean = S * invN;
        float var  = Q * invN - mean * mean;
        float sc = bn3_g[f] * rsqrtf(var + BN_EPS);
        sscale[f] = sc;
        sshift[f] = bn3_b[f] - mean * sc;
    }
    __syncthreads();
    const int warp = t >> 5, lane = t & 31;
    const int b = blockIdx.x * 8 + warp;
    float h[16];
    #pragma unroll
    for (int i = 0; i < 16; i++) {
        int f = lane + 32 * i;
        float v = g_fc1[b * F1 + f];
        h[i] = fmaxf(fmaf(sscale[f], v, sshift[f]), 0.0f);
    }
    #pragma unroll
    for (int o = 0; o < F2; o++) {
        float acc = 0.f;
        #pragma unroll
        for (int i = 0; i < 16; i++)
            acc = fmaf(h[i], swq[o * F1 + lane + 32 * i], acc);
        #pragma unroll
        for (int s = 16; s; s >>= 1)
            acc += __shfl_xor_sync(0xffffffffu, acc, s);
        if (lane == 0) out[b * F2 + o] = acc + sbias[o];
    }
}

// ---------------- PDL launch helper ----------------
template <typename... Args>
static void pdl_launch(void (*kern)(Args...), dim3 g, dim3 b, size_t smem, Args... args) {
    cudaLaunchConfig_t cfg = {};
    cfg.gridDim = g; cfg.blockDim = b; cfg.dynamicSmemBytes = smem; cfg.stream = 0;
    cudaLaunchAttribute at[1];
    at[0].id = cudaLaunchAttributeProgrammaticStreamSerialization;
    at[0].val.programmaticStreamSerializationAllowed = 1;
    cfg.attrs = at; cfg.numAttrs = 1;
    cudaLaunchKernelEx(&cfg, kern, args...);
}

// ---------------- launcher ----------------
extern "C" void kernel_launch(void* const* d_in, const int* in_sizes, int n_in,
                              void* d_out, int out_size) {
    const float* x       = (const float*)d_in[0];
    const float* conv1_w = (const float*)d_in[1];
    const float* bn1_g   = (const float*)d_in[3];
    const float* bn1_b   = (const float*)d_in[4];
    const float* conv2_w = (const float*)d_in[5];
    const float* bn2_g   = (const float*)d_in[7];
    const float* bn2_b   = (const float*)d_in[8];
    const float* fc1_w   = (const float*)d_in[9];
    const float* bn3_g   = (const float*)d_in[11];
    const float* bn3_b   = (const float*)d_in[12];
    const float* fc2_w   = (const float*)d_in[13];
    const float* fc2_b   = (const float*)d_in[14];
    float* out = (float*)d_out;

    cudaFuncSetAttribute(k_conv1, cudaFuncAttributeMaxDynamicSharedMemorySize, CV1_SMEM_BYTES);
    cudaFuncSetAttribute(k_conv2, cudaFuncAttributeMaxDynamicSharedMemorySize, CV2_SMEM_BYTES);

    // quantization (conv/fc biases dropped: train-mode BN cancels them exactly)
    pdl_launch(k_absmax_all, dim3(128, 4), dim3(256), 0, conv1_w, conv2_w, fc1_w, fc2_w);
    pdl_launch(k_quant_all,  dim3(128, 3), dim3(256), 0, conv2_w, fc1_w, fc2_w);

    // stage 1 (conv1 self-quantizes its weights: runs concurrent with quant via PDL)
    pdl_launch(k_conv1, dim3(B), dim3(256), (size_t)CV1_SMEM_BYTES, x, conv1_w);
    pdl_launch(k_bnfin1, dim3(8), dim3(256), 0, bn1_g, bn1_b);

    // stage 2 (weight staging overlaps bnfin1 via PDL)
    pdl_launch(k_conv2, dim3(B / 2), dim3(256), (size_t)CV2_SMEM_BYTES);
    pdl_launch(k_bnfin2, dim3(16), dim3(256), 0, bn2_g, bn2_b);

    // stage 3 (fc1 B-staging overlaps bnfin2; fc2 weight load overlaps fc1)
    pdl_launch(k_fc1, dim3(16, 8), dim3(256), 0);
    pdl_launch(k_fc2, dim3(B / 8), dim3(256), 0, fc2_b, bn3_g, bn3_b, out);
}

// round 12
// speedup vs baseline: 1.4892x; 1.0925x over previous
#include <cuda_runtime.h>
#include <cuda_fp16.h>
#include <cuda_bf16.h>

// ---------------- problem constants ----------------
#define B      512
#define C1     64
#define C2     128
#define FLAT   2048
#define F1     512
#define F2     10
#define BN_EPS 1e-5f

// ---------------- device scratch ----------------
__device__ unsigned g_maxabs[4];                  // slots 1..3; zero-init; atomicMax idempotent
__device__ __half g_qw2h[25 * C2 * C1];           // conv2 ternary [khkw][oc][ci]
__device__ __half g_qf1h[F1 * FLAT];              // fc1 ternary [f][k]
__device__ float  g_qf2[F2 * F1];
__device__ float g_pool1[B * 144 * C1];           // RAW pooled conv1 (pre-BN), [b][pixel][ci]
__device__ float g_p1sum[C1 * B], g_p1sq[C1 * B];
__device__ float g_scale1[C1], g_shift1[C1];
__device__ float g_p2sum[C2 * B], g_p2sq[C2 * B];
__device__ float g_scale2[C2], g_shift2[C2];
__device__ float g_h1[B * FLAT];                  // RAW pooled conv2 (pre-BN)
__device__ float g_fc1[B * F1];                   // RAW fc1 (pre-BN)
__device__ float g_p3s[F1 * 16], g_p3q[F1 * 16];  // BN3 partials: [feature][b-tile]

// ---------------- cp.async helpers ----------------
__device__ __forceinline__ void cp16(__half* smem_dst, const __half* gsrc) {
    unsigned s = (unsigned)__cvta_generic_to_shared(smem_dst);
    asm volatile("cp.async.cg.shared.global [%0], [%1], 16;\n" :: "r"(s), "l"(gsrc));
}
#define CP_COMMIT() asm volatile("cp.async.commit_group;\n" ::: "memory")
#define CP_WAIT0()  asm volatile("cp.async.wait_group 0;\n" ::: "memory")

// ---------------- quantization (slots 1..3: conv2, fc1, fc2 weights) ----------------
__global__ void k_absmax_all(const float* __restrict__ w1, const float* __restrict__ w2,
                             const float* __restrict__ w3) {
    cudaTriggerProgrammaticLaunchCompletion();
    const int slot = blockIdx.y + 1;
    const float* w = (slot == 1) ? w1 : (slot == 2) ? w2 : w3;
    const int n4 = ((slot == 1) ? 204800 : (slot == 2) ? 1048576 : 5120) >> 2;
    const float4* w4 = (const float4*)w;
    unsigned m = 0u;
    #pragma unroll 4
    for (int i = blockIdx.x * blockDim.x + threadIdx.x; i < n4; i += gridDim.x * blockDim.x) {
        float4 v = w4[i];
        m = max(m, __float_as_uint(fabsf(v.x)));
        m = max(m, __float_as_uint(fabsf(v.y)));
        m = max(m, __float_as_uint(fabsf(v.z)));
        m = max(m, __float_as_uint(fabsf(v.w)));
    }
    #pragma unroll
    for (int o = 16; o; o >>= 1)
        m = max(m, __shfl_xor_sync(0xffffffffu, m, o));
    if ((threadIdx.x & 31) == 0) atomicMax(&g_maxabs[slot], m);
}

__global__ void k_quant_all(const float* __restrict__ w1,
                            const float* __restrict__ w2, const float* __restrict__ w3) {
    cudaTriggerProgrammaticLaunchCompletion();   // conv1 is self-contained: safe to cascade
    cudaGridDependencySynchronize();             // need g_maxabs from absmax
    const int slot = blockIdx.y + 1;
    const float* w = (slot == 1) ? w1 : (slot == 2) ? w2 : w3;
    const int n4 = ((slot == 1) ? 204800 : (slot == 2) ? 1048576 : 5120) >> 2;
    const float4* w4 = (const float4*)w;
    const float t = 0.05f * __uint_as_float(g_maxabs[slot]);
    #pragma unroll 2
    for (int i = blockIdx.x * blockDim.x + threadIdx.x; i < n4; i += gridDim.x * blockDim.x) {
        float4 v = w4[i];
        float q0 = (v.x > t) ? 1.0f : ((v.x < -t) ? -1.0f : 0.0f);
        float q1 = (v.y > t) ? 1.0f : ((v.y < -t) ? -1.0f : 0.0f);
        float q2 = (v.z > t) ? 1.0f : ((v.z < -t) ? -1.0f : 0.0f);
        float q3 = (v.w > t) ? 1.0f : ((v.w < -t) ? -1.0f : 0.0f);
        int base = 4 * i;
        if (slot == 1) {
            float qs[4] = {q0, q1, q2, q3};
            #pragma unroll
            for (int u = 0; u < 4; u++) {
                int idx = base + u;
                int oc = idx / 1600, rem = idx - oc * 1600, ci = rem / 25, kk = rem - ci * 25;
                g_qw2h[kk * (C2 * C1) + oc * C1 + ci] = __float2half(qs[u]);
            }
        } else if (slot == 2) {
            *(__half2*)&g_qf1h[base]     = __floats2half2_rn(q0, q1);
            *(__half2*)&g_qf1h[base + 2] = __floats2half2_rn(q2, q3);
        } else {
            *(float4*)&g_qf2[base] = make_float4(q0, q1, q2, q3);
        }
    }
}

// ---------------- conv1: fp16 mma; fully self-contained (own absmax + quant) ------------
// Reads ONLY x and raw conv1 weights -> no gridDepSync; overlaps absmax AND quant via PDL.
// max is order-independent -> threshold (and thus everything downstream) bit-identical.
#define CV1_SMEM_BYTES (3136 + 5120 + 46080)
__global__ __launch_bounds__(256) void k_conv1(const float* __restrict__ x,
                                               const float* __restrict__ w1raw) {
    cudaTriggerProgrammaticLaunchCompletion();
    extern __shared__ char c1sm[];
    float*  sxf = (float*)c1sm;
    __half* sA  = (__half*)(c1sm + 3136);
    __half* sB  = (__half*)(c1sm + 3136 + 5120);
    __shared__ float srs[64][9], srq[64][9];
    __shared__ unsigned swm[8];
    const int b = blockIdx.x, t = threadIdx.x;
    const int lane = t & 31, warp = t >> 5;
    const int l4 = lane >> 2, lm4 = lane & 3;

    for (int i = t; i < 784; i += 256) sxf[i] = x[b * 784 + i];
    // in-block absmax of conv1 weights (exact: unsigned-termwise max of abs bits)
    {
        unsigned mm = 0u;
        for (int i = t; i < 1600; i += 256) mm = max(mm, __float_as_uint(fabsf(w1raw[i])));
        #pragma unroll
        for (int o = 16; o; o >>= 1) mm = max(mm, __shfl_xor_sync(0xffffffffu, mm, o));
        if (lane == 0) swm[warp] = mm;
    }
    __syncthreads();
    {
        unsigned m8 = swm[0];
        #pragma unroll
        for (int j = 1; j < 8; j++) m8 = max(m8, swm[j]);
        const float tq = 0.05f * __uint_as_float(m8);
        for (int i = t; i < 1600; i += 256) {
            int oc = i / 25, k = i - oc * 25;
            float v = w1raw[i];
            sA[oc * 40 + k] = __float2half((v > tq) ? 1.0f : ((v < -tq) ? -1.0f : 0.0f));
        }
        for (int i = t; i < 64 * 7; i += 256) {   // zero pad k=25..31
            int oc = i / 7, k = 25 + i % 7;
            sA[oc * 40 + k] = __ushort_as_half((unsigned short)0);
        }
    }
    // im2col (reads sxf — visible since the syncthreads above)
    {
        const int kp = t & 15, n0 = t >> 4;
        const int k0 = 2 * kp;
        const int kh0 = k0 / 5, kw0 = k0 - 5 * kh0;
        const int kh1 = (k0 + 1) / 5, kw1 = (k0 + 1) - 5 * kh1;
        const bool e0 = (k0 < 25), e1 = (k0 + 1 < 25);
        #pragma unroll 4
        for (int st = 0; st < 36; st++) {
            int n = n0 + 16 * st;
            int w = n >> 2, j = n & 3;
            int py = w / 12, px = w - 12 * py;
            int iy = 2 * py + (j >> 1), ix = 2 * px + (j & 1);
            float v0 = e0 ? sxf[(iy + kh0) * 28 + ix + kw0] : 0.f;
            float v1 = e1 ? sxf[(iy + kh1) * 28 + ix + kw1] : 0.f;
            *(__half2*)&sB[n * 40 + k0] = __floats2half2_rn(v0, v1);
        }
    }
    __syncthreads();

    unsigned a[4][2][4];
    #pragma unroll
    for (int mt = 0; mt < 4; mt++) {
        const __half* ap = sA + (mt * 16 + l4) * 40 + 2 * lm4;
        #pragma unroll
        for (int ks = 0; ks < 2; ks++) {
            a[mt][ks][0] = *(const unsigned*)(ap + 16 * ks);
            a[mt][ks][1] = *(const unsigned*)(ap + 16 * ks + 8 * 40);
            a[mt][ks][2] = *(const unsigned*)(ap + 16 * ks + 8);
            a[mt][ks][3] = *(const unsigned*)(ap + 16 * ks + 8 * 40 + 8);
        }
    }

    float s0a[4] = {0,0,0,0}, s1a[4] = {0,0,0,0};
    float q0a[4] = {0,0,0,0}, q1a[4] = {0,0,0,0};

    #pragma unroll
    for (int nt = 0; nt < 9; nt++) {
        const __half* bp = sB + (warp * 72 + nt * 8 + l4) * 40 + 2 * lm4;
        unsigned bf[2][2];
        #pragma unroll
        for (int ks = 0; ks < 2; ks++) {
            bf[ks][0] = *(const unsigned*)(bp + 16 * ks);
            bf[ks][1] = *(const unsigned*)(bp + 16 * ks + 8);
        }
        float c[4][4];
        #pragma unroll
        for (int mt = 0; mt < 4; mt++) {
            c[mt][0] = c[mt][1] = c[mt][2] = c[mt][3] = 0.f;
            #pragma unroll
            for (int ks = 0; ks < 2; ks++)
                asm volatile(
                    "mma.sync.aligned.m16n8k16.row.col.f32.f16.f16.f32 "
                    "{%0,%1,%2,%3},{%4,%5,%6,%7},{%8,%9},{%0,%1,%2,%3};"
                    : "+f"(c[mt][0]), "+f"(c[mt][1]), "+f"(c[mt][2]), "+f"(c[mt][3])
                    : "r"(a[mt][ks][0]), "r"(a[mt][ks][1]), "r"(a[mt][ks][2]), "r"(a[mt][ks][3]),
                      "r"(bf[ks][0]), "r"(bf[ks][1]));
        }
        const int wdw = warp * 18 + nt * 2 + (lm4 >> 1);
        #pragma unroll
        for (int mt = 0; mt < 4; mt++) {
            s0a[mt] += c[mt][0] + c[mt][1];
            q0a[mt] += c[mt][0]*c[mt][0] + c[mt][1]*c[mt][1];
            s1a[mt] += c[mt][2] + c[mt][3];
            q1a[mt] += c[mt][2]*c[mt][2] + c[mt][3]*c[mt][3];
            float m0 = fmaxf(c[mt][0], c[mt][1]);
            float m1 = fmaxf(c[mt][2], c[mt][3]);
            m0 = fmaxf(m0, __shfl_xor_sync(0xffffffffu, m0, 1));
            m1 = fmaxf(m1, __shfl_xor_sync(0xffffffffu, m1, 1));
            if ((lm4 & 1) == 0) {
                int oc = mt * 16 + l4;
                g_pool1[b * 9216 + wdw * 64 + oc]     = m0;
                g_pool1[b * 9216 + wdw * 64 + oc + 8] = m1;
            }
        }
    }

    #pragma unroll
    for (int mt = 0; mt < 4; mt++) {
        float s0 = s0a[mt], q0 = q0a[mt], s1 = s1a[mt], q1 = q1a[mt];
        s0 += __shfl_xor_sync(0xffffffffu, s0, 1); s0 += __shfl_xor_sync(0xffffffffu, s0, 2);
        q0 += __shfl_xor_sync(0xffffffffu, q0, 1); q0 += __shfl_xor_sync(0xffffffffu, q0, 2);
        s1 += __shfl_xor_sync(0xffffffffu, s1, 1); s1 += __shfl_xor_sync(0xffffffffu, s1, 2);
        q1 += __shfl_xor_sync(0xffffffffu, q1, 1); q1 += __shfl_xor_sync(0xffffffffu, q1, 2);
        if (lm4 == 0) {
            srs[mt * 16 + l4][warp] = s0;     srq[mt * 16 + l4][warp] = q0;
            srs[mt * 16 + l4 + 8][warp] = s1; srq[mt * 16 + l4 + 8][warp] = q1;
        }
    }
    __syncthreads();
    if (t < 64) {
        float S = 0.f, Q = 0.f;
        #pragma unroll
        for (int w = 0; w < 8; w++) { S += srs[t][w]; Q += srq[t][w]; }
        g_p1sum[t * B + b] = S;
        g_p1sq [t * B + b] = Q;
    }
}

// ---------------- BN finalize: warp-per-channel; trigger AFTER sync (gates cascade) -----
__global__ void k_bnfin1(const float* __restrict__ gamma, const float* __restrict__ beta) {
    cudaGridDependencySynchronize();             // all prior work (incl. quant, conv1) done
    cudaTriggerProgrammaticLaunchCompletion();   // now conv2 may launch: its staging is safe
    const int w = threadIdx.x >> 5, lane = threadIdx.x & 31;
    const int c = blockIdx.x * 8 + w;
    const float4* ps = (const float4*)&g_p1sum[c * B];
    const float4* pq = (const float4*)&g_p1sq [c * B];
    float s = 0.f, q = 0.f;
    #pragma unroll
    for (int i = 0; i < 4; i++) {
        float4 v = ps[lane * 4 + i]; s += v.x + v.y + v.z + v.w;
        float4 u = pq[lane * 4 + i]; q += u.x + u.y + u.z + u.w;
    }
    #pragma unroll
    for (int o = 16; o; o >>= 1) {
        s += __shfl_xor_sync(0xffffffffu, s, o);
        q += __shfl_xor_sync(0xffffffffu, q, o);
    }
    if (lane == 0) {
        const float invN = 1.0f / (float)(B * 576);
        float mean = s * invN;
        float var  = q * invN - mean * mean;
        float sc = gamma[c] * rsqrtf(var + BN_EPS);
        g_scale1[c] = sc;
        g_shift1[c] = beta[c] - mean * sc;
    }
}

__global__ void k_bnfin2(const float* __restrict__ gamma, const float* __restrict__ beta) {
    cudaGridDependencySynchronize();             // all prior work (incl. conv2) done
    cudaTriggerProgrammaticLaunchCompletion();   // now fc1 may launch: its staging is safe
    const int w = threadIdx.x >> 5, lane = threadIdx.x & 31;
    const int c = blockIdx.x * 8 + w;
    const float4* ps = (const float4*)&g_p2sum[c * B];
    const float4* pq = (const float4*)&g_p2sq [c * B];
    float s = 0.f, q = 0.f;
    #pragma unroll
    for (int i = 0; i < 4; i++) {
        float4 v = ps[lane * 4 + i]; s += v.x + v.y + v.z + v.w;
        float4 u = pq[lane * 4 + i]; q += u.x + u.y + u.z + u.w;
    }
    #pragma unroll
    for (int o = 16; o; o >>= 1) {
        s += __shfl_xor_sync(0xffffffffu, s, o);
        q += __shfl_xor_sync(0xffffffffu, q, o);
    }
    if (lane == 0) {
        const float invN = 1.0f / (float)(B * 64);
        float mean = s * invN;
        float var  = q * invN - mean * mean;
        float sc = gamma[c] * rsqrtf(var + BN_EPS);
        g_scale2[c] = sc;
        g_shift2[c] = beta[c] - mean * sc;
    }
}

// ---------------- conv2: fp16 mma, 2 images/block, 256 threads, 2 blocks/SM -------------
#define CV2_CSTR 72
#define CV2_IMGH (144 * CV2_CSTR)
#define CV2_SX_H (2 * CV2_IMGH)
#define CV2_WBUF (C2 * CV2_CSTR)
#define CV2_SMEM_BYTES ((CV2_SX_H + 2 * CV2_WBUF) * 2)

__global__ __launch_bounds__(256, 2) void k_conv2() {
    cudaTriggerProgrammaticLaunchCompletion();
    extern __shared__ __half smh[];
    __half* sxh = smh;
    __half* sA0 = smh + CV2_SX_H;
    __half* sA1 = sA0 + CV2_WBUF;
    const int b2 = blockIdx.x * 2;
    const int t = threadIdx.x;
    const int lane = t & 31, warp = t >> 5;
    const int l4 = lane >> 2, lm4 = lane & 3;
    const int wm = warp >> 2, wn = warp & 3;
    const int img = wn >> 1, yh = wn & 1;
    const int m0w = wm * 64;

    {   // weights: quant provably complete (we launched after bnfin1's post-sync trigger)
        const __half* wsrc = g_qw2h;
        #pragma unroll
        for (int j = 0; j < 4; j++) {
            int idx = t + 256 * j;
            int oc = idx >> 3, c8 = idx & 7;
            cp16(sA0 + oc * CV2_CSTR + c8 * 8, wsrc + idx * 8);
        }
        CP_COMMIT();
    }

    cudaGridDependencySynchronize();             // need scale1/shift1 from bnfin1

    for (int idx = t; idx < 2 * 144 * 32; idx += 256) {
        int im = idx / 4608, r = idx - im * 4608;
        int p = r >> 5, cp = r & 31;
        int ci0 = 2 * cp;
        float2 v = *(const float2*)&g_pool1[(b2 + im) * 9216 + p * 64 + ci0];
        float v0 = fmaxf(fmaf(g_scale1[ci0],     v.x, g_shift1[ci0]),     0.0f);
        float v1 = fmaxf(fmaf(g_scale1[ci0 + 1], v.y, g_shift1[ci0 + 1]), 0.0f);
        *(__half2*)&sxh[im * CV2_IMGH + p * CV2_CSTR + ci0] = __floats2half2_rn(v0, v1);
    }

    float c[4][4][4];
    #pragma unroll
    for (int i = 0; i < 4; i++)
        #pragma unroll
        for (int j = 0; j < 4; j++)
            #pragma unroll
            for (int r = 0; r < 4; r++) c[i][j][r] = 0.f;

    for (int khkw = 0; khkw < 25; khkw++) {
        const __half* sA = (khkw & 1) ? sA1 : sA0;
        CP_WAIT0();
        __syncthreads();
        if (khkw < 24) {
            __half* dst = (khkw & 1) ? sA0 : sA1;
            const __half* wsrc = g_qw2h + (khkw + 1) * (C2 * C1);
            #pragma unroll
            for (int j = 0; j < 4; j++) {
                int idx = t + 256 * j;
                int oc = idx >> 3, c8 = idx & 7;
                cp16(dst + oc * CV2_CSTR + c8 * 8, wsrc + idx * 8);
            }
            CP_COMMIT();
        }
        const int kh = khkw / 5, kw = khkw - 5 * kh;
        const __half* bbase = sxh + img * CV2_IMGH
                            + ((yh * 4 + kh) * 12 + kw + l4) * CV2_CSTR + 2 * lm4;
        #pragma unroll
        for (int ks = 0; ks < 4; ks++) {
            const int k0 = ks * 16;
            unsigned a[4][4], bf[4][2];
            #pragma unroll
            for (int mt = 0; mt < 4; mt++) {
                const __half* ap = sA + (m0w + mt * 16 + l4) * CV2_CSTR + k0 + 2 * lm4;
                a[mt][0] = *(const unsigned*)(ap);
                a[mt][1] = *(const unsigned*)(ap + 8 * CV2_CSTR);
                a[mt][2] = *(const unsigned*)(ap + 8);
                a[mt][3] = *(const unsigned*)(ap + 8 * CV2_CSTR + 8);
            }
            const __half* bp = bbase + k0;
            #pragma unroll
            for (int nt = 0; nt < 4; nt++) {
                bf[nt][0] = *(const unsigned*)(bp + nt * 12 * CV2_CSTR);
                bf[nt][1] = *(const unsigned*)(bp + nt * 12 * CV2_CSTR + 8);
            }
            #pragma unroll
            for (int mt = 0; mt < 4; mt++)
                #pragma unroll
                for (int nt = 0; nt < 4; nt++)
                    asm volatile(
                        "mma.sync.aligned.m16n8k16.row.col.f32.f16.f16.f32 "
                        "{%0,%1,%2,%3},{%4,%5,%6,%7},{%8,%9},{%0,%1,%2,%3};"
                        : "+f"(c[mt][nt][0]), "+f"(c[mt][nt][1]),
                          "+f"(c[mt][nt][2]), "+f"(c[mt][nt][3])
                        : "r"(a[mt][0]), "r"(a[mt][1]), "r"(a[mt][2]), "r"(a[mt][3]),
                          "r"(bf[nt][0]), "r"(bf[nt][1]));
        }
    }

    __syncthreads();
    float* sps = (float*)sA0;
    float* spq = sps + 512;
    const int bimg = b2 + img;
    #pragma unroll
    for (int mt = 0; mt < 4; mt++) {
        int r0 = m0w + mt * 16 + l4;
        #pragma unroll
        for (int tp = 0; tp < 2; tp++) {
            float pA = fmaxf(fmaxf(c[mt][2*tp][0], c[mt][2*tp][1]),
                             fmaxf(c[mt][2*tp+1][0], c[mt][2*tp+1][1]));
            float pB = fmaxf(fmaxf(c[mt][2*tp][2], c[mt][2*tp][3]),
                             fmaxf(c[mt][2*tp+1][2], c[mt][2*tp+1][3]));
            int gy = yh * 2 + tp;
            g_h1[bimg * FLAT + r0 * 16 + gy * 4 + lm4] = pA;
            g_h1[bimg * FLAT + (r0 + 8) * 16 + gy * 4 + lm4] = pB;
        }
        float s0 = 0.f, q0 = 0.f, s1 = 0.f, q1 = 0.f;
        #pragma unroll
        for (int nt = 0; nt < 4; nt++) {
            s0 += c[mt][nt][0] + c[mt][nt][1];
            q0 += c[mt][nt][0]*c[mt][nt][0] + c[mt][nt][1]*c[mt][nt][1];
            s1 += c[mt][nt][2] + c[mt][nt][3];
            q1 += c[mt][nt][2]*c[mt][nt][2] + c[mt][nt][3]*c[mt][nt][3];
        }
        s0 += __shfl_xor_sync(0xffffffffu, s0, 1); s0 += __shfl_xor_sync(0xffffffffu, s0, 2);
        q0 += __shfl_xor_sync(0xffffffffu, q0, 1); q0 += __shfl_xor_sync(0xffffffffu, q0, 2);
        s1 += __shfl_xor_sync(0xffffffffu, s1, 1); s1 += __shfl_xor_sync(0xffffffffu, s1, 2);
        q1 += __shfl_xor_sync(0xffffffffu, q1, 1); q1 += __shfl_xor_sync(0xffffffffu, q1, 2);
        if (lm4 == 0) {
            sps[(yh * 128 + r0) * 2 + img] = s0;       spq[(yh * 128 + r0) * 2 + img] = q0;
            sps[(yh * 128 + r0 + 8) * 2 + img] = s1;   spq[(yh * 128 + r0 + 8) * 2 + img] = q1;
        }
    }
    __syncthreads();
    {
        int oc = t >> 1, im = t & 1;
        float S = sps[(oc) * 2 + im] + sps[(128 + oc) * 2 + im];
        float Q = spq[(oc) * 2 + im] + spq[(128 + oc) * 2 + im];
        g_p2sum[oc * B + b2 + im] = S;
        g_p2sq [oc * B + b2 + im] = Q;
    }
}

// ---------------- fc1: fp16 mma, 32-row b-tiles (grid 16x8), BN3 partials in epilogue ---
#define FC1_STR 136
__global__ __launch_bounds__(256) void k_fc1() {
    cudaTriggerProgrammaticLaunchCompletion();
    __shared__ __half sA[32 * FC1_STR];
    __shared__ __half sB[64 * FC1_STR];
    const int t = threadIdx.x;
    const int lane = t & 31, warp = t >> 5;
    const int l4 = lane >> 2, lm4 = lane & 3;
    const int wm = warp >> 2, wn = warp & 3;
    const int b0 = blockIdx.x * 32, f0 = blockIdx.y * 64;
    const int m0w = wm * 16, n0w = wn * 16;

    float c[2][4];
    #pragma unroll
    for (int j = 0; j < 2; j++)
        #pragma unroll
        for (int r = 0; r < 4; r++) c[j][r] = 0.f;

    for (int kc = 0; kc < 16; kc++) {
        if (kc) __syncthreads();
        // B first (weights provably complete; on kc==0 overlaps bnfin2 execution)
        #pragma unroll
        for (int j = 0; j < 4; j++) {
            int idx = t + 256 * j;
            int fl = idx >> 4, k8 = idx & 15;
            *(uint4*)&sB[fl * FC1_STR + k8 * 8] =
                *(const uint4*)&g_qf1h[(f0 + fl) * FLAT + kc * 128 + k8 * 8];
        }
        if (kc == 0) cudaGridDependencySynchronize();   // need scale2/shift2 from bnfin2
        #pragma unroll
        for (int j = 0; j < 8; j++) {
            int idx = t + 256 * j;
            int bl = idx >> 6, kp = idx & 63;
            int kg = kc * 128 + 2 * kp;
            float2 v = *(const float2*)&g_h1[(b0 + bl) * FLAT + kg];
            int c0 = kg >> 4, c1 = (kg + 1) >> 4;
            float v0 = fmaxf(fmaf(g_scale2[c0], v.x, g_shift2[c0]), 0.0f);
            float v1 = fmaxf(fmaf(g_scale2[c1], v.y, g_shift2[c1]), 0.0f);
            *(__half2*)&sA[bl * FC1_STR + 2 * kp] = __floats2half2_rn(v0, v1);
        }
        __syncthreads();
        #pragma unroll
        for (int ks = 0; ks < 8; ks++) {
            const int k0 = ks * 16;
            unsigned a[4], bf[2][2];
            {
                const __half* ap = sA + (m0w + l4) * FC1_STR + k0 + 2 * lm4;
                a[0] = *(const unsigned*)(ap);
                a[1] = *(const unsigned*)(ap + 8 * FC1_STR);
                a[2] = *(const unsigned*)(ap + 8);
                a[3] = *(const unsigned*)(ap + 8 * FC1_STR + 8);
            }
            #pragma unroll
            for (int nt = 0; nt < 2; nt++) {
                const __half* bp = sB + (n0w + nt * 8 + l4) * FC1_STR + k0 + 2 * lm4;
                bf[nt][0] = *(const unsigned*)(bp);
                bf[nt][1] = *(const unsigned*)(bp + 8);
            }
            #pragma unroll
            for (int nt = 0; nt < 2; nt++)
                asm volatile(
                    "mma.sync.aligned.m16n8k16.row.col.f32.f16.f16.f32 "
                    "{%0,%1,%2,%3},{%4,%5,%6,%7},{%8,%9},{%0,%1,%2,%3};"
                    : "+f"(c[nt][0]), "+f"(c[nt][1]), "+f"(c[nt][2]), "+f"(c[nt][3])
                    : "r"(a[0]), "r"(a[1]), "r"(a[2]), "r"(a[3]),
                      "r"(bf[nt][0]), "r"(bf[nt][1]));
        }
    }
    {
        int rA = b0 + m0w + l4;
        #pragma unroll
        for (int nt = 0; nt < 2; nt++) {
            int cc = f0 + n0w + nt * 8 + 2 * lm4;
            *(float2*)&g_fc1[rA * F1 + cc]       = make_float2(c[nt][0], c[nt][1]);
            *(float2*)&g_fc1[(rA + 8) * F1 + cc] = make_float2(c[nt][2], c[nt][3]);
        }
    }
    __syncthreads();
    float* srs = (float*)sB;
    float* srq = srs + 128;
    #pragma unroll
    for (int nt = 0; nt < 2; nt++) {
        #pragma unroll
        for (int j = 0; j < 2; j++) {
            float s = c[nt][j] + c[nt][j + 2];
            float q = c[nt][j]*c[nt][j] + c[nt][j+2]*c[nt][j+2];
            #pragma unroll
            for (int o = 4; o < 32; o <<= 1) {
                s += __shfl_xor_sync(0xffffffffu, s, o);
                q += __shfl_xor_sync(0xffffffffu, q, o);
            }
            if (l4 == 0) {
                int fl = n0w + nt * 8 + 2 * lm4 + j;
                srs[wm * 64 + fl] = s;
                srq[wm * 64 + fl] = q;
            }
        }
    }
    __syncthreads();
    if (t < 64) {
        float S = srs[t] + srs[64 + t];
        float Q = srq[t] + srq[64 + t];
        g_p3s[(f0 + t) * 16 + blockIdx.x] = S;
        g_p3q[(f0 + t) * 16 + blockIdx.x] = Q;
    }
}

// ---------------- fc2: BN3 finalize (redundant per block) + bn3+relu+fc2 ----------------
__global__ __launch_bounds__(256) void k_fc2(const float* __restrict__ fc2_b,
                                             const float* __restrict__ bn3_g,
                                             const float* __restrict__ bn3_b,
                                             float* __restrict__ out) {
    cudaTriggerProgrammaticLaunchCompletion();
    __shared__ float swq[F2 * F1];
    __shared__ float sscale[F1], sshift[F1];
    __shared__ float sbias[F2];
    const int t = threadIdx.x;
    for (int i = t; i < F2 * F1; i += 256) swq[i] = g_qf2[i];   // quant done: overlap fc1
    if (t < F2) sbias[t] = fc2_b[t];
    cudaGridDependencySynchronize();             // need g_p3s/g_p3q/g_fc1 from fc1
    #pragma unroll
    for (int j = 0; j < 2; j++) {
        int f = t + 256 * j;
        float S = 0.f, Q = 0.f;
        #pragma unroll
        for (int u = 0; u < 4; u++) {
            float4 sv = *(const float4*)&g_p3s[f * 16 + 4 * u];
            float4 qv = *(const float4*)&g_p3q[f * 16 + 4 * u];
            S += sv.x + sv.y + sv.z + sv.w;
            Q += qv.x + qv.y + qv.z + qv.w;
        }
        const float invN = 1.0f / (float)B;
        float mean = S * invN;
        float var  = Q * invN - mean * mean;
        float sc = bn3_g[f] * rsqrtf(var + BN_EPS);
        sscale[f] = sc;
        sshift[f] = bn3_b[f] - mean * sc;
    }
    __syncthreads();
    const int warp = t >> 5, lane = t & 31;
    const int b = blockIdx.x * 8 + warp;
    float h[16];
    #pragma unroll
    for (int i = 0; i < 16; i++) {
        int f = lane + 32 * i;
        float v = g_fc1[b * F1 + f];
        h[i] = fmaxf(fmaf(sscale[f], v, sshift[f]), 0.0f);
    }
    #pragma unroll
    for (int o = 0; o < F2; o++) {
        float acc = 0.f;
        #pragma unroll
        for (int i = 0; i < 16; i++)
            acc = fmaf(h[i], swq[o * F1 + lane + 32 * i], acc);
        #pragma unroll
        for (int s = 16; s; s >>= 1)
            acc += __shfl_xor_sync(0xffffffffu, acc, s);
        if (lane == 0) out[b * F2 + o] = acc + sbias[o];
    }
}

// ---------------- PDL launch helper ----------------
template <typename... Args>
static void pdl_launch(void (*kern)(Args...), dim3 g, dim3 b, size_t smem, Args... args) {
    cudaLaunchConfig_t cfg = {};
    cfg.gridDim = g; cfg.blockDim = b; cfg.dynamicSmemBytes = smem; cfg.stream = 0;
    cudaLaunchAttribute at[1];
    at[0].id = cudaLaunchAttributeProgrammaticStreamSerialization;
    at[0].val.programmaticStreamSerializationAllowed = 1;
    cfg.attrs = at; cfg.numAttrs = 1;
    cudaLaunchKernelEx(&cfg, kern, args...);
}

// ---------------- launcher ----------------
extern "C" void kernel_launch(void* const* d_in, const int* in_sizes, int n_in,
                              void* d_out, int out_size) {
    const float* x       = (const float*)d_in[0];
    const float* conv1_w = (const float*)d_in[1];
    const float* bn1_g   = (const float*)d_in[3];
    const float* bn1_b   = (const float*)d_in[4];
    const float* conv2_w = (const float*)d_in[5];
    const float* bn2_g   = (const float*)d_in[7];
    const float* bn2_b   = (const float*)d_in[8];
    const float* fc1_w   = (const float*)d_in[9];
    const float* bn3_g   = (const float*)d_in[11];
    const float* bn3_b   = (const float*)d_in[12];
    const float* fc2_w   = (const float*)d_in[13];
    const float* fc2_b   = (const float*)d_in[14];
    float* out = (float*)d_out;

    cudaFuncSetAttribute(k_conv1, cudaFuncAttributeMaxDynamicSharedMemorySize, CV1_SMEM_BYTES);
    cudaFuncSetAttribute(k_conv2, cudaFuncAttributeMaxDynamicSharedMemorySize, CV2_SMEM_BYTES);

    // weight quantization for conv2/fc1/fc2 (conv1 self-quantizes inside k_conv1)
    pdl_launch(k_absmax_all, dim3(128, 3), dim3(256), 0, conv2_w, fc1_w, fc2_w);
    pdl_launch(k_quant_all,  dim3(128, 3), dim3(256), 0, conv2_w, fc1_w, fc2_w);

    // stage 1: conv1 is dependency-free -> overlaps absmax AND quant
    pdl_launch(k_conv1, dim3(B), dim3(256), (size_t)CV1_SMEM_BYTES, x, conv1_w);
    pdl_launch(k_bnfin1, dim3(8), dim3(256), 0, bn1_g, bn1_b);   // gates cascade

    // stage 2 (weight staging overlaps bnfin1 execution)
    pdl_launch(k_conv2, dim3(B / 2), dim3(256), (size_t)CV2_SMEM_BYTES);
    pdl_launch(k_bnfin2, dim3(16), dim3(256), 0, bn2_g, bn2_b);  // gates cascade

    // stage 3 (fc1 B-staging overlaps bnfin2; fc2 weight load overlaps fc1)
    pdl_launch(k_fc1, dim3(16, 8), dim3(256), 0);
    pdl_launch(k_fc2, dim3(B / 8), dim3(256), 0, fc2_b, bn3_g, bn3_b, out);
}

// round 13
// speedup vs baseline: 1.6591x; 1.1141x over previous
#include <cuda_runtime.h>
#include <cuda_fp16.h>
#include <cuda_bf16.h>

// ---------------- problem constants ----------------
#define B      512
#define C1     64
#define C2     128
#define FLAT   2048
#define F1     512
#define F2     10
#define BN_EPS 1e-5f

// ---------------- device scratch ----------------
__device__ unsigned g_maxabs[4];                  // slots 1..3; zero-init; atomicMax idempotent
__device__ __half g_qw2h[25 * C2 * C1];           // conv2 ternary [khkw][oc][ci]
__device__ __half g_qf1h[F1 * FLAT];              // fc1 ternary [f][k]
__device__ float  g_qf2[F2 * F1];
__device__ float g_pool1[B * 144 * C1];           // RAW pooled conv1 (pre-BN), [b][pixel][ci]
__device__ float g_p1sum[C1 * B], g_p1sq[C1 * B];
__device__ float g_scale1[C1], g_shift1[C1];
__device__ float g_p2sum[C2 * B], g_p2sq[C2 * B];
__device__ float g_scale2[C2], g_shift2[C2];
__device__ float g_h1[B * FLAT];                  // RAW pooled conv2 (pre-BN)
__device__ float g_fc1[B * F1];                   // RAW fc1 (pre-BN)
__device__ float g_p3s[F1 * 16], g_p3q[F1 * 16];  // BN3 partials: [feature][b-tile]

// ---------------- asm helpers ----------------
__device__ __forceinline__ void cp16(__half* smem_dst, const __half* gsrc) {
    unsigned s = (unsigned)__cvta_generic_to_shared(smem_dst);
    asm volatile("cp.async.cg.shared.global [%0], [%1], 16;\n" :: "r"(s), "l"(gsrc));
}
#define CP_COMMIT() asm volatile("cp.async.commit_group;\n" ::: "memory")
#define CP_WAIT0()  asm volatile("cp.async.wait_group 0;\n" ::: "memory")

__device__ __forceinline__ void ldsm4(unsigned& r0, unsigned& r1, unsigned& r2, unsigned& r3,
                                      unsigned saddr) {
    asm volatile("ldmatrix.sync.aligned.m8n8.x4.shared.b16 {%0,%1,%2,%3}, [%4];"
                 : "=r"(r0), "=r"(r1), "=r"(r2), "=r"(r3) : "r"(saddr));
}
__device__ __forceinline__ void ldsm2(unsigned& r0, unsigned& r1, unsigned saddr) {
    asm volatile("ldmatrix.sync.aligned.m8n8.x2.shared.b16 {%0,%1}, [%2];"
                 : "=r"(r0), "=r"(r1) : "r"(saddr));
}

// ---------------- quantization (slots 1..3: conv2, fc1, fc2 weights) ----------------
__global__ void k_absmax_all(const float* __restrict__ w1, const float* __restrict__ w2,
                             const float* __restrict__ w3) {
    cudaTriggerProgrammaticLaunchCompletion();
    const int slot = blockIdx.y + 1;
    const float* w = (slot == 1) ? w1 : (slot == 2) ? w2 : w3;
    const int n4 = ((slot == 1) ? 204800 : (slot == 2) ? 1048576 : 5120) >> 2;
    const float4* w4 = (const float4*)w;
    unsigned m = 0u;
    #pragma unroll 4
    for (int i = blockIdx.x * blockDim.x + threadIdx.x; i < n4; i += gridDim.x * blockDim.x) {
        float4 v = w4[i];
        m = max(m, __float_as_uint(fabsf(v.x)));
        m = max(m, __float_as_uint(fabsf(v.y)));
        m = max(m, __float_as_uint(fabsf(v.z)));
        m = max(m, __float_as_uint(fabsf(v.w)));
    }
    #pragma unroll
    for (int o = 16; o; o >>= 1)
        m = max(m, __shfl_xor_sync(0xffffffffu, m, o));
    if ((threadIdx.x & 31) == 0) atomicMax(&g_maxabs[slot], m);
}

__global__ void k_quant_all(const float* __restrict__ w1,
                            const float* __restrict__ w2, const float* __restrict__ w3) {
    cudaTriggerProgrammaticLaunchCompletion();   // conv1 is self-contained: safe to cascade
    cudaGridDependencySynchronize();             // need g_maxabs from absmax
    const int slot = blockIdx.y + 1;
    const float* w = (slot == 1) ? w1 : (slot == 2) ? w2 : w3;
    const int n4 = ((slot == 1) ? 204800 : (slot == 2) ? 1048576 : 5120) >> 2;
    const float4* w4 = (const float4*)w;
    const float t = 0.05f * __uint_as_float(g_maxabs[slot]);
    #pragma unroll 2
    for (int i = blockIdx.x * blockDim.x + threadIdx.x; i < n4; i += gridDim.x * blockDim.x) {
        float4 v = w4[i];
        float q0 = (v.x > t) ? 1.0f : ((v.x < -t) ? -1.0f : 0.0f);
        float q1 = (v.y > t) ? 1.0f : ((v.y < -t) ? -1.0f : 0.0f);
        float q2 = (v.z > t) ? 1.0f : ((v.z < -t) ? -1.0f : 0.0f);
        float q3 = (v.w > t) ? 1.0f : ((v.w < -t) ? -1.0f : 0.0f);
        int base = 4 * i;
        if (slot == 1) {
            float qs[4] = {q0, q1, q2, q3};
            #pragma unroll
            for (int u = 0; u < 4; u++) {
                int idx = base + u;
                int oc = idx / 1600, rem = idx - oc * 1600, ci = rem / 25, kk = rem - ci * 25;
                g_qw2h[kk * (C2 * C1) + oc * C1 + ci] = __float2half(qs[u]);
            }
        } else if (slot == 2) {
            *(__half2*)&g_qf1h[base]     = __floats2half2_rn(q0, q1);
            *(__half2*)&g_qf1h[base + 2] = __floats2half2_rn(q2, q3);
        } else {
            *(float4*)&g_qf2[base] = make_float4(q0, q1, q2, q3);
        }
    }
}

// ---------------- conv1: fp16 mma; fully self-contained (own absmax + quant) ------------
#define CV1_SMEM_BYTES (3136 + 5120 + 46080)
__global__ __launch_bounds__(256) void k_conv1(const float* __restrict__ x,
                                               const float* __restrict__ w1raw) {
    cudaTriggerProgrammaticLaunchCompletion();
    extern __shared__ char c1sm[];
    float*  sxf = (float*)c1sm;
    __half* sA  = (__half*)(c1sm + 3136);
    __half* sB  = (__half*)(c1sm + 3136 + 5120);
    __shared__ float srs[64][9], srq[64][9];
    __shared__ unsigned swm[8];
    const int b = blockIdx.x, t = threadIdx.x;
    const int lane = t & 31, warp = t >> 5;
    const int l4 = lane >> 2, lm4 = lane & 3;

    for (int i = t; i < 784; i += 256) sxf[i] = x[b * 784 + i];
    {
        unsigned mm = 0u;
        for (int i = t; i < 1600; i += 256) mm = max(mm, __float_as_uint(fabsf(w1raw[i])));
        #pragma unroll
        for (int o = 16; o; o >>= 1) mm = max(mm, __shfl_xor_sync(0xffffffffu, mm, o));
        if (lane == 0) swm[warp] = mm;
    }
    __syncthreads();
    {
        unsigned m8 = swm[0];
        #pragma unroll
        for (int j = 1; j < 8; j++) m8 = max(m8, swm[j]);
        const float tq = 0.05f * __uint_as_float(m8);
        for (int i = t; i < 1600; i += 256) {
            int oc = i / 25, k = i - oc * 25;
            float v = w1raw[i];
            sA[oc * 40 + k] = __float2half((v > tq) ? 1.0f : ((v < -tq) ? -1.0f : 0.0f));
        }
        for (int i = t; i < 64 * 7; i += 256) {
            int oc = i / 7, k = 25 + i % 7;
            sA[oc * 40 + k] = __ushort_as_half((unsigned short)0);
        }
    }
    {
        const int kp = t & 15, n0 = t >> 4;
        const int k0 = 2 * kp;
        const int kh0 = k0 / 5, kw0 = k0 - 5 * kh0;
        const int kh1 = (k0 + 1) / 5, kw1 = (k0 + 1) - 5 * kh1;
        const bool e0 = (k0 < 25), e1 = (k0 + 1 < 25);
        #pragma unroll 4
        for (int st = 0; st < 36; st++) {
            int n = n0 + 16 * st;
            int w = n >> 2, j = n & 3;
            int py = w / 12, px = w - 12 * py;
            int iy = 2 * py + (j >> 1), ix = 2 * px + (j & 1);
            float v0 = e0 ? sxf[(iy + kh0) * 28 + ix + kw0] : 0.f;
            float v1 = e1 ? sxf[(iy + kh1) * 28 + ix + kw1] : 0.f;
            *(__half2*)&sB[n * 40 + k0] = __floats2half2_rn(v0, v1);
        }
    }
    __syncthreads();

    unsigned a[4][2][4];
    #pragma unroll
    for (int mt = 0; mt < 4; mt++) {
        const __half* ap = sA + (mt * 16 + l4) * 40 + 2 * lm4;
        #pragma unroll
        for (int ks = 0; ks < 2; ks++) {
            a[mt][ks][0] = *(const unsigned*)(ap + 16 * ks);
            a[mt][ks][1] = *(const unsigned*)(ap + 16 * ks + 8 * 40);
            a[mt][ks][2] = *(const unsigned*)(ap + 16 * ks + 8);
            a[mt][ks][3] = *(const unsigned*)(ap + 16 * ks + 8 * 40 + 8);
        }
    }

    float s0a[4] = {0,0,0,0}, s1a[4] = {0,0,0,0};
    float q0a[4] = {0,0,0,0}, q1a[4] = {0,0,0,0};

    #pragma unroll
    for (int nt = 0; nt < 9; nt++) {
        const __half* bp = sB + (warp * 72 + nt * 8 + l4) * 40 + 2 * lm4;
        unsigned bf[2][2];
        #pragma unroll
        for (int ks = 0; ks < 2; ks++) {
            bf[ks][0] = *(const unsigned*)(bp + 16 * ks);
            bf[ks][1] = *(const unsigned*)(bp + 16 * ks + 8);
        }
        float c[4][4];
        #pragma unroll
        for (int mt = 0; mt < 4; mt++) {
            c[mt][0] = c[mt][1] = c[mt][2] = c[mt][3] = 0.f;
            #pragma unroll
            for (int ks = 0; ks < 2; ks++)
                asm volatile(
                    "mma.sync.aligned.m16n8k16.row.col.f32.f16.f16.f32 "
                    "{%0,%1,%2,%3},{%4,%5,%6,%7},{%8,%9},{%0,%1,%2,%3};"
                    : "+f"(c[mt][0]), "+f"(c[mt][1]), "+f"(c[mt][2]), "+f"(c[mt][3])
                    : "r"(a[mt][ks][0]), "r"(a[mt][ks][1]), "r"(a[mt][ks][2]), "r"(a[mt][ks][3]),
                      "r"(bf[ks][0]), "r"(bf[ks][1]));
        }
        const int wdw = warp * 18 + nt * 2 + (lm4 >> 1);
        #pragma unroll
        for (int mt = 0; mt < 4; mt++) {
            s0a[mt] += c[mt][0] + c[mt][1];
            q0a[mt] += c[mt][0]*c[mt][0] + c[mt][1]*c[mt][1];
            s1a[mt] += c[mt][2] + c[mt][3];
            q1a[mt] += c[mt][2]*c[mt][2] + c[mt][3]*c[mt][3];
            float m0 = fmaxf(c[mt][0], c[mt][1]);
            float m1 = fmaxf(c[mt][2], c[mt][3]);
            m0 = fmaxf(m0, __shfl_xor_sync(0xffffffffu, m0, 1));
            m1 = fmaxf(m1, __shfl_xor_sync(0xffffffffu, m1, 1));
            if ((lm4 & 1) == 0) {
                int oc = mt * 16 + l4;
                g_pool1[b * 9216 + wdw * 64 + oc]     = m0;
                g_pool1[b * 9216 + wdw * 64 + oc + 8] = m1;
            }
        }
    }

    #pragma unroll
    for (int mt = 0; mt < 4; mt++) {
        float s0 = s0a[mt], q0 = q0a[mt], s1 = s1a[mt], q1 = q1a[mt];
        s0 += __shfl_xor_sync(0xffffffffu, s0, 1); s0 += __shfl_xor_sync(0xffffffffu, s0, 2);
        q0 += __shfl_xor_sync(0xffffffffu, q0, 1); q0 += __shfl_xor_sync(0xffffffffu, q0, 2);
        s1 += __shfl_xor_sync(0xffffffffu, s1, 1); s1 += __shfl_xor_sync(0xffffffffu, s1, 2);
        q1 += __shfl_xor_sync(0xffffffffu, q1, 1); q1 += __shfl_xor_sync(0xffffffffu, q1, 2);
        if (lm4 == 0) {
            srs[mt * 16 + l4][warp] = s0;     srq[mt * 16 + l4][warp] = q0;
            srs[mt * 16 + l4 + 8][warp] = s1; srq[mt * 16 + l4 + 8][warp] = q1;
        }
    }
    __syncthreads();
    if (t < 64) {
        float S = 0.f, Q = 0.f;
        #pragma unroll
        for (int w = 0; w < 8; w++) { S += srs[t][w]; Q += srq[t][w]; }
        g_p1sum[t * B + b] = S;
        g_p1sq [t * B + b] = Q;
    }
}

// ---------------- BN finalize: ONE 32-thread block per channel (same reduction order) ---
__global__ void k_bnfin1(const float* __restrict__ gamma, const float* __restrict__ beta) {
    cudaGridDependencySynchronize();             // all prior work done
    cudaTriggerProgrammaticLaunchCompletion();   // gate: conv2 may launch now
    const int lane = threadIdx.x & 31;
    const int c = blockIdx.x;
    const float4* ps = (const float4*)&g_p1sum[c * B];
    const float4* pq = (const float4*)&g_p1sq [c * B];
    float s = 0.f, q = 0.f;
    #pragma unroll
    for (int i = 0; i < 4; i++) {
        float4 v = ps[lane * 4 + i]; s += v.x + v.y + v.z + v.w;
        float4 u = pq[lane * 4 + i]; q += u.x + u.y + u.z + u.w;
    }
    #pragma unroll
    for (int o = 16; o; o >>= 1) {
        s += __shfl_xor_sync(0xffffffffu, s, o);
        q += __shfl_xor_sync(0xffffffffu, q, o);
    }
    if (lane == 0) {
        const float invN = 1.0f / (float)(B * 576);
        float mean = s * invN;
        float var  = q * invN - mean * mean;
        float sc = gamma[c] * rsqrtf(var + BN_EPS);
        g_scale1[c] = sc;
        g_shift1[c] = beta[c] - mean * sc;
    }
}

__global__ void k_bnfin2(const float* __restrict__ gamma, const float* __restrict__ beta) {
    cudaGridDependencySynchronize();
    cudaTriggerProgrammaticLaunchCompletion();   // gate: fc1 may launch now
    const int lane = threadIdx.x & 31;
    const int c = blockIdx.x;
    const float4* ps = (const float4*)&g_p2sum[c * B];
    const float4* pq = (const float4*)&g_p2sq [c * B];
    float s = 0.f, q = 0.f;
    #pragma unroll
    for (int i = 0; i < 4; i++) {
        float4 v = ps[lane * 4 + i]; s += v.x + v.y + v.z + v.w;
        float4 u = pq[lane * 4 + i]; q += u.x + u.y + u.z + u.w;
    }
    #pragma unroll
    for (int o = 16; o; o >>= 1) {
        s += __shfl_xor_sync(0xffffffffu, s, o);
        q += __shfl_xor_sync(0xffffffffu, q, o);
    }
    if (lane == 0) {
        const float invN = 1.0f / (float)(B * 64);
        float mean = s * invN;
        float var  = q * invN - mean * mean;
        float sc = gamma[c] * rsqrtf(var + BN_EPS);
        g_scale2[c] = sc;
        g_shift2[c] = beta[c] - mean * sc;
    }
}

// ---------------- conv2: fp16 mma + ldmatrix frags, 2 images/block, 2 blocks/SM ---------
#define CV2_CSTR 72
#define CV2_IMGH (144 * CV2_CSTR)
#define CV2_SX_H (2 * CV2_IMGH)
#define CV2_WBUF (C2 * CV2_CSTR)
#define CV2_SMEM_BYTES ((CV2_SX_H + 2 * CV2_WBUF) * 2)

__global__ __launch_bounds__(256, 2) void k_conv2() {
    cudaTriggerProgrammaticLaunchCompletion();
    extern __shared__ __half smh[];
    __half* sxh = smh;
    __half* sA0 = smh + CV2_SX_H;
    __half* sA1 = sA0 + CV2_WBUF;
    const int b2 = blockIdx.x * 2;
    const int t = threadIdx.x;
    const int lane = t & 31, warp = t >> 5;
    const int l4 = lane >> 2, lm4 = lane & 3;
    const int wm = warp >> 2, wn = warp & 3;
    const int img = wn >> 1, yh = wn & 1;
    const int m0w = wm * 64;

    {   // weights provably complete (launched after bnfin1's post-sync trigger)
        const __half* wsrc = g_qw2h;
        #pragma unroll
        for (int j = 0; j < 4; j++) {
            int idx = t + 256 * j;
            int oc = idx >> 3, c8 = idx & 7;
            cp16(sA0 + oc * CV2_CSTR + c8 * 8, wsrc + idx * 8);
        }
        CP_COMMIT();
    }

    cudaGridDependencySynchronize();             // need scale1/shift1 from bnfin1

    for (int idx = t; idx < 2 * 144 * 32; idx += 256) {
        int im = idx / 4608, r = idx - im * 4608;
        int p = r >> 5, cp = r & 31;
        int ci0 = 2 * cp;
        float2 v = *(const float2*)&g_pool1[(b2 + im) * 9216 + p * 64 + ci0];
        float v0 = fmaxf(fmaf(g_scale1[ci0],     v.x, g_shift1[ci0]),     0.0f);
        float v1 = fmaxf(fmaf(g_scale1[ci0 + 1], v.y, g_shift1[ci0 + 1]), 0.0f);
        *(__half2*)&sxh[im * CV2_IMGH + p * CV2_CSTR + ci0] = __floats2half2_rn(v0, v1);
    }

    float c[4][4][4];
    #pragma unroll
    for (int i = 0; i < 4; i++)
        #pragma unroll
        for (int j = 0; j < 4; j++)
            #pragma unroll
            for (int r = 0; r < 4; r++) c[i][j][r] = 0.f;

    // ldmatrix byte addresses (shared space); frag bit-layouts identical to manual loads
    const unsigned sxa  = (unsigned)__cvta_generic_to_shared(sxh);
    const unsigned sA0a = (unsigned)__cvta_generic_to_shared(sA0);
    const unsigned sA1a = (unsigned)__cvta_generic_to_shared(sA1);
    const unsigned aoff = (unsigned)((m0w + (lane & 15)) * CV2_CSTR) * 2u + (((unsigned)lane >> 4) << 4);
    const unsigned bln  = (unsigned)((lane & 7) * CV2_CSTR) * 2u + ((((unsigned)lane >> 3) & 1u) << 4);

    for (int khkw = 0; khkw < 25; khkw++) {
        const unsigned sAa = (khkw & 1) ? sA1a : sA0a;
        CP_WAIT0();
        __syncthreads();
        if (khkw < 24) {
            __half* dst = (khkw & 1) ? sA0 : sA1;
            const __half* wsrc = g_qw2h + (khkw + 1) * (C2 * C1);
            #pragma unroll
            for (int j = 0; j < 4; j++) {
                int idx = t + 256 * j;
                int oc = idx >> 3, c8 = idx & 7;
                cp16(dst + oc * CV2_CSTR + c8 * 8, wsrc + idx * 8);
            }
            CP_COMMIT();
        }
        const int kh = khkw / 5, kw = khkw - 5 * kh;
        const unsigned bbase = sxa
            + (unsigned)(img * CV2_IMGH + ((yh * 4 + kh) * 12 + kw) * CV2_CSTR) * 2u + bln;
        #pragma unroll
        for (int ks = 0; ks < 4; ks++) {
            const unsigned k0b = (unsigned)(ks * 32);
            unsigned a[4][4], bf[4][2];
            #pragma unroll
            for (int mt = 0; mt < 4; mt++)
                ldsm4(a[mt][0], a[mt][1], a[mt][2], a[mt][3],
                      sAa + aoff + (unsigned)(mt * 16 * CV2_CSTR * 2) + k0b);
            #pragma unroll
            for (int nt = 0; nt < 4; nt++)
                ldsm2(bf[nt][0], bf[nt][1],
                      bbase + (unsigned)(nt * 12 * CV2_CSTR * 2) + k0b);
            #pragma unroll
            for (int mt = 0; mt < 4; mt++)
                #pragma unroll
                for (int nt = 0; nt < 4; nt++)
                    asm volatile(
                        "mma.sync.aligned.m16n8k16.row.col.f32.f16.f16.f32 "
                        "{%0,%1,%2,%3},{%4,%5,%6,%7},{%8,%9},{%0,%1,%2,%3};"
                        : "+f"(c[mt][nt][0]), "+f"(c[mt][nt][1]),
                          "+f"(c[mt][nt][2]), "+f"(c[mt][nt][3])
                        : "r"(a[mt][0]), "r"(a[mt][1]), "r"(a[mt][2]), "r"(a[mt][3]),
                          "r"(bf[nt][0]), "r"(bf[nt][1]));
        }
    }

    __syncthreads();
    float* sps = (float*)sA0;
    float* spq = sps + 512;
    const int bimg = b2 + img;
    #pragma unroll
    for (int mt = 0; mt < 4; mt++) {
        int r0 = m0w + mt * 16 + l4;
        #pragma unroll
        for (int tp = 0; tp < 2; tp++) {
            float pA = fmaxf(fmaxf(c[mt][2*tp][0], c[mt][2*tp][1]),
                             fmaxf(c[mt][2*tp+1][0], c[mt][2*tp+1][1]));
            float pB = fmaxf(fmaxf(c[mt][2*tp][2], c[mt][2*tp][3]),
                             fmaxf(c[mt][2*tp+1][2], c[mt][2*tp+1][3]));
            int gy = yh * 2 + tp;
            g_h1[bimg * FLAT + r0 * 16 + gy * 4 + lm4] = pA;
            g_h1[bimg * FLAT + (r0 + 8) * 16 + gy * 4 + lm4] = pB;
        }
        float s0 = 0.f, q0 = 0.f, s1 = 0.f, q1 = 0.f;
        #pragma unroll
        for (int nt = 0; nt < 4; nt++) {
            s0 += c[mt][nt][0] + c[mt][nt][1];
            q0 += c[mt][nt][0]*c[mt][nt][0] + c[mt][nt][1]*c[mt][nt][1];
            s1 += c[mt][nt][2] + c[mt][nt][3];
            q1 += c[mt][nt][2]*c[mt][nt][2] + c[mt][nt][3]*c[mt][nt][3];
        }
        s0 += __shfl_xor_sync(0xffffffffu, s0, 1); s0 += __shfl_xor_sync(0xffffffffu, s0, 2);
        q0 += __shfl_xor_sync(0xffffffffu, q0, 1); q0 += __shfl_xor_sync(0xffffffffu, q0, 2);
        s1 += __shfl_xor_sync(0xffffffffu, s1, 1); s1 += __shfl_xor_sync(0xffffffffu, s1, 2);
        q1 += __shfl_xor_sync(0xffffffffu, q1, 1); q1 += __shfl_xor_sync(0xffffffffu, q1, 2);
        if (lm4 == 0) {
            sps[(yh * 128 + r0) * 2 + img] = s0;       spq[(yh * 128 + r0) * 2 + img] = q0;
            sps[(yh * 128 + r0 + 8) * 2 + img] = s1;   spq[(yh * 128 + r0 + 8) * 2 + img] = q1;
        }
    }
    __syncthreads();
    {
        int oc = t >> 1, im = t & 1;
        float S = sps[(oc) * 2 + im] + sps[(128 + oc) * 2 + im];
        float Q = spq[(oc) * 2 + im] + spq[(128 + oc) * 2 + im];
        g_p2sum[oc * B + b2 + im] = S;
        g_p2sq [oc * B + b2 + im] = Q;
    }
}

// ---------------- fc1: fp16 mma + ldmatrix frags, 32-row b-tiles (grid 16x8) ------------
#define FC1_STR 136
__global__ __launch_bounds__(256) void k_fc1() {
    cudaTriggerProgrammaticLaunchCompletion();
    __shared__ __align__(16) __half sA[32 * FC1_STR];
    __shared__ __align__(16) __half sB[64 * FC1_STR];
    const int t = threadIdx.x;
    const int lane = t & 31, warp = t >> 5;
    const int l4 = lane >> 2, lm4 = lane & 3;
    const int wm = warp >> 2, wn = warp & 3;
    const int b0 = blockIdx.x * 32, f0 = blockIdx.y * 64;
    const int m0w = wm * 16, n0w = wn * 16;

    const unsigned sAa = (unsigned)__cvta_generic_to_shared(sA);
    const unsigned sBa = (unsigned)__cvta_generic_to_shared(sB);
    const unsigned aoff = (unsigned)((m0w + (lane & 15)) * FC1_STR) * 2u + (((unsigned)lane >> 4) << 4);
    const unsigned boff = (unsigned)((n0w + (lane & 7)) * FC1_STR) * 2u + ((((unsigned)lane >> 3) & 1u) << 4);

    float c[2][4];
    #pragma unroll
    for (int j = 0; j < 2; j++)
        #pragma unroll
        for (int r = 0; r < 4; r++) c[j][r] = 0.f;

    for (int kc = 0; kc < 16; kc++) {
        if (kc) __syncthreads();
        // B first (weights provably complete; on kc==0 overlaps bnfin2 execution)
        #pragma unroll
        for (int j = 0; j < 4; j++) {
            int idx = t + 256 * j;
            int fl = idx >> 4, k8 = idx & 15;
            *(uint4*)&sB[fl * FC1_STR + k8 * 8] =
                *(const uint4*)&g_qf1h[(f0 + fl) * FLAT + kc * 128 + k8 * 8];
        }
        if (kc == 0) cudaGridDependencySynchronize();   // need scale2/shift2 from bnfin2
        #pragma unroll
        for (int j = 0; j < 8; j++) {
            int idx = t + 256 * j;
            int bl = idx >> 6, kp = idx & 63;
            int kg = kc * 128 + 2 * kp;
            float2 v = *(const float2*)&g_h1[(b0 + bl) * FLAT + kg];
            int c0 = kg >> 4, c1 = (kg + 1) >> 4;
            float v0 = fmaxf(fmaf(g_scale2[c0], v.x, g_shift2[c0]), 0.0f);
            float v1 = fmaxf(fmaf(g_scale2[c1], v.y, g_shift2[c1]), 0.0f);
            *(__half2*)&sA[bl * FC1_STR + 2 * kp] = __floats2half2_rn(v0, v1);
        }
        __syncthreads();
        #pragma unroll
        for (int ks = 0; ks < 8; ks++) {
            const unsigned k0b = (unsigned)(ks * 32);
            unsigned a[4], bf[2][2];
            ldsm4(a[0], a[1], a[2], a[3], sAa + aoff + k0b);
            #pragma unroll
            for (int nt = 0; nt < 2; nt++)
                ldsm2(bf[nt][0], bf[nt][1],
                      sBa + boff + (unsigned)(nt * 8 * FC1_STR * 2) + k0b);
            #pragma unroll
            for (int nt = 0; nt < 2; nt++)
                asm volatile(
                    "mma.sync.aligned.m16n8k16.row.col.f32.f16.f16.f32 "
                    "{%0,%1,%2,%3},{%4,%5,%6,%7},{%8,%9},{%0,%1,%2,%3};"
                    : "+f"(c[nt][0]), "+f"(c[nt][1]), "+f"(c[nt][2]), "+f"(c[nt][3])
                    : "r"(a[0]), "r"(a[1]), "r"(a[2]), "r"(a[3]),
                      "r"(bf[nt][0]), "r"(bf[nt][1]));
        }
    }
    {
        int rA = b0 + m0w + l4;
        #pragma unroll
        for (int nt = 0; nt < 2; nt++) {
            int cc = f0 + n0w + nt * 8 + 2 * lm4;
            *(float2*)&g_fc1[rA * F1 + cc]       = make_float2(c[nt][0], c[nt][1]);
            *(float2*)&g_fc1[(rA + 8) * F1 + cc] = make_float2(c[nt][2], c[nt][3]);
        }
    }
    __syncthreads();
    float* srs = (float*)sB;
    float* srq = srs + 128;
    #pragma unroll
    for (int nt = 0; nt < 2; nt++) {
        #pragma unroll
        for (int j = 0; j < 2; j++) {
            float s = c[nt][j] + c[nt][j + 2];
            float q = c[nt][j]*c[nt][j] + c[nt][j+2]*c[nt][j+2];
            #pragma unroll
            for (int o = 4; o < 32; o <<= 1) {
                s += __shfl_xor_sync(0xffffffffu, s, o);
                q += __shfl_xor_sync(0xffffffffu, q, o);
            }
            if (l4 == 0) {
                int fl = n0w + nt * 8 + 2 * lm4 + j;
                srs[wm * 64 + fl] = s;
                srq[wm * 64 + fl] = q;
            }
        }
    }
    __syncthreads();
    if (t < 64) {
        float S = srs[t] + srs[64 + t];
        float Q = srq[t] + srq[64 + t];
        g_p3s[(f0 + t) * 16 + blockIdx.x] = S;
        g_p3q[(f0 + t) * 16 + blockIdx.x] = Q;
    }
}

// ---------------- fc2: BN3 finalize (redundant per block) + bn3+relu+fc2 ----------------
__global__ __launch_bounds__(256) void k_fc2(const float* __restrict__ fc2_b,
                                             const float* __restrict__ bn3_g,
                                             const float* __restrict__ bn3_b,
                                             float* __restrict__ out) {
    cudaTriggerProgrammaticLaunchCompletion();
    __shared__ float swq[F2 * F1];
    __shared__ float sscale[F1], sshift[F1];
    __shared__ float sbias[F2];
    const int t = threadIdx.x;
    for (int i = t; i < F2 * F1; i += 256) swq[i] = g_qf2[i];   // quant done: overlap fc1
    if (t < F2) sbias[t] = fc2_b[t];
    cudaGridDependencySynchronize();             // need g_p3s/g_p3q/g_fc1 from fc1
    #pragma unroll
    for (int j = 0; j < 2; j++) {
        int f = t + 256 * j;
        float S = 0.f, Q = 0.f;
        #pragma unroll
        for (int u = 0; u < 4; u++) {
            float4 sv = *(const float4*)&g_p3s[f * 16 + 4 * u];
            float4 qv = *(const float4*)&g_p3q[f * 16 + 4 * u];
            S += sv.x + sv.y + sv.z + sv.w;
            Q += qv.x + qv.y + qv.z + qv.w;
        }
        const float invN = 1.0f / (float)B;
        float mean = S * invN;
        float var  = Q * invN - mean * mean;
        float sc = bn3_g[f] * rsqrtf(var + BN_EPS);
        sscale[f] = sc;
        sshift[f] = bn3_b[f] - mean * sc;
    }
    __syncthreads();
    const int warp = t >> 5, lane = t & 31;
    const int b = blockIdx.x * 8 + warp;
    float h[16];
    #pragma unroll
    for (int i = 0; i < 16; i++) {
        int f = lane + 32 * i;
        float v = g_fc1[b * F1 + f];
        h[i] = fmaxf(fmaf(sscale[f], v, sshift[f]), 0.0f);
    }
    #pragma unroll
    for (int o = 0; o < F2; o++) {
        float acc = 0.f;
        #pragma unroll
        for (int i = 0; i < 16; i++)
            acc = fmaf(h[i], swq[o * F1 + lane + 32 * i], acc);
        #pragma unroll
        for (int s = 16; s; s >>= 1)
            acc += __shfl_xor_sync(0xffffffffu, acc, s);
        if (lane == 0) out[b * F2 + o] = acc + sbias[o];
    }
}

// ---------------- PDL launch helper ----------------
template <typename... Args>
static void pdl_launch(void (*kern)(Args...), dim3 g, dim3 b, size_t smem, Args... args) {
    cudaLaunchConfig_t cfg = {};
    cfg.gridDim = g; cfg.blockDim = b; cfg.dynamicSmemBytes = smem; cfg.stream = 0;
    cudaLaunchAttribute at[1];
    at[0].id = cudaLaunchAttributeProgrammaticStreamSerialization;
    at[0].val.programmaticStreamSerializationAllowed = 1;
    cfg.attrs = at; cfg.numAttrs = 1;
    cudaLaunchKernelEx(&cfg, kern, args...);
}

// ---------------- launcher ----------------
extern "C" void kernel_launch(void* const* d_in, const int* in_sizes, int n_in,
                              void* d_out, int out_size) {
    const float* x       = (const float*)d_in[0];
    const float* conv1_w = (const float*)d_in[1];
    const float* bn1_g   = (const float*)d_in[3];
    const float* bn1_b   = (const float*)d_in[4];
    const float* conv2_w = (const float*)d_in[5];
    const float* bn2_g   = (const float*)d_in[7];
    const float* bn2_b   = (const float*)d_in[8];
    const float* fc1_w   = (const float*)d_in[9];
    const float* bn3_g   = (const float*)d_in[11];
    const float* bn3_b   = (const float*)d_in[12];
    const float* fc2_w   = (const float*)d_in[13];
    const float* fc2_b   = (const float*)d_in[14];
    float* out = (float*)d_out;

    cudaFuncSetAttribute(k_conv1, cudaFuncAttributeMaxDynamicSharedMemorySize, CV1_SMEM_BYTES);
    cudaFuncSetAttribute(k_conv2, cudaFuncAttributeMaxDynamicSharedMemorySize, CV2_SMEM_BYTES);

    // weight quantization for conv2/fc1/fc2 (conv1 self-quantizes inside k_conv1)
    pdl_launch(k_absmax_all, dim3(128, 3), dim3(256), 0, conv2_w, fc1_w, fc2_w);
    pdl_launch(k_quant_all,  dim3(128, 3), dim3(256), 0, conv2_w, fc1_w, fc2_w);

    // stage 1: conv1 is dependency-free -> overlaps absmax AND quant
    pdl_launch(k_conv1, dim3(B), dim3(256), (size_t)CV1_SMEM_BYTES, x, conv1_w);
    pdl_launch(k_bnfin1, dim3(C1), dim3(32), 0, bn1_g, bn1_b);   // gates cascade

    // stage 2 (weight staging overlaps bnfin1 execution)
    pdl_launch(k_conv2, dim3(B / 2), dim3(256), (size_t)CV2_SMEM_BYTES);
    pdl_launch(k_bnfin2, dim3(C2), dim3(32), 0, bn2_g, bn2_b);   // gates cascade

    // stage 3 (fc1 B-staging overlaps bnfin2; fc2 weight load overlaps fc1)
    pdl_launch(k_fc1, dim3(16, 8), dim3(256), 0);
    pdl_launch(k_fc2, dim3(B / 8), dim3(256), 0, fc2_b, bn3_g, bn3_b, out);
}